// round 11
// baseline (speedup 1.0000x reference)
#include <cuda_runtime.h>
#include <cuda_bf16.h>
#include <cstdint>

#define Bb   8
#define Nn   2048
#define Cc   64
#define MIDm 256
#define KK   16
#define R2c  0.0225f
#define EPSc 1e-5f

// ---------------- scratch (device globals, no allocation) ----------------
__device__ __align__(16) int    g_idx[Bb*Nn*KK];      // [b][n][16]
__device__ __align__(16) float  g_feat[Bb*Nn*Cc];     // [b][n][c]  = w1[:,3:]@f
__device__ __align__(16) float  g_m[Bb*Cc*Nn];        // [b][c][n]  = max_k x
__device__ __align__(16) float  g_y[Bb*MIDm*Nn];      // [b][c][n]
__device__ __align__(16) float  g_z[Bb*Cc*Nn];        // [b][c][n]
// split-bf16 weights (same layout as source, no transpose needed)
__device__ __align__(16) __nv_bfloat16 g_w2h[MIDm*Cc], g_w2l[MIDm*Cc];   // [o=256][k=64]
__device__ __align__(16) __nv_bfloat16 g_w3h[Cc*MIDm], g_w3l[Cc*MIDm];   // [c=64][k=256]
__device__ double g_s1[Cc],   g_ss1[Cc];
__device__ double g_s2[MIDm], g_ss2[MIDm];
__device__ double g_s3[Cc],   g_ss3[Cc];

// ---------------- mma/ldmatrix helpers ----------------
__device__ __forceinline__ uint32_t smem_u32(const void* p) {
    uint32_t r;
    asm("{ .reg .u64 t; cvta.to.shared.u64 t, %1; cvt.u32.u64 %0, t; }" : "=r"(r) : "l"(p));
    return r;
}
__device__ __forceinline__ void ldmB(uint32_t* b2, uint32_t addr) {  // x2 trans
    asm volatile("ldmatrix.sync.aligned.m8n8.x2.trans.shared.b16 {%0,%1}, [%2];"
                 : "=r"(b2[0]), "=r"(b2[1]) : "r"(addr));
}
__device__ __forceinline__ void mma16816(float* d, const uint32_t* a, const uint32_t* b2) {
    asm volatile(
        "mma.sync.aligned.m16n8k16.row.col.f32.bf16.bf16.f32 "
        "{%0,%1,%2,%3}, {%4,%5,%6,%7}, {%8,%9}, {%0,%1,%2,%3};"
        : "+f"(d[0]), "+f"(d[1]), "+f"(d[2]), "+f"(d[3])
        : "r"(a[0]), "r"(a[1]), "r"(a[2]), "r"(a[3]), "r"(b2[0]), "r"(b2[1]));
}
__device__ __forceinline__ void split_bf16(float v, __nv_bfloat16& h, __nv_bfloat16& l) {
    h = __float2bfloat16_rn(v);
    l = __float2bfloat16_rn(v - __bfloat162float(h));
}
__device__ __forceinline__ uint32_t pack2(__nv_bfloat16 a, __nv_bfloat16 b) {
    return (uint32_t)__bfloat16_as_ushort(a) | ((uint32_t)__bfloat16_as_ushort(b) << 16);
}
__device__ __forceinline__ uint32_t ldg_u32(const __nv_bfloat16* p) {
    return __ldg((const uint32_t*)p);
}
// A fragment (m16k16, row-major) direct from global, per PTX fragment spec.
// base = row-major [rows][ldk] bf16 array; r = tile row base; kb = ks*16 + (lane&3)*2; g = lane>>2.
__device__ __forceinline__ void ldA_frag(uint32_t* a, const __nv_bfloat16* base,
                                         int ldk, int r, int g, int kb) {
    a[0] = ldg_u32(base + (size_t)(r + g)*ldk + kb);
    a[1] = ldg_u32(base + (size_t)(r + g + 8)*ldk + kb);
    a[2] = ldg_u32(base + (size_t)(r + g)*ldk + kb + 8);
    a[3] = ldg_u32(base + (size_t)(r + g + 8)*ldk + kb + 8);
}

// ---------------- K_gfeat (+prep in blocks<64) ----------------
__global__ void __launch_bounds__(256) k_gfeat(const float* __restrict__ f,
                                               const float* __restrict__ w1,
                                               const float* __restrict__ w2,
                                               const float* __restrict__ w3) {
    __shared__ __align__(16) float w1t[64*68];
    __shared__ __align__(16) float fs[64*32];
    __shared__ __align__(16) float gs[32*68];
    int tid = threadIdx.x;
    int b  = blockIdx.x >> 6;
    int n0 = (blockIdx.x & 63) << 5;

    if (blockIdx.x < 64) {
        int i = blockIdx.x * 256 + tid;          // 0..16383
        { __nv_bfloat16 h, l; split_bf16(w2[i], h, l); g_w2h[i] = h; g_w2l[i] = l; }
        { __nv_bfloat16 h, l; split_bf16(w3[i], h, l); g_w3h[i] = h; g_w3l[i] = l; }
        if (i < Cc)   { g_s1[i]=0.0; g_ss1[i]=0.0; g_s3[i]=0.0; g_ss3[i]=0.0; }
        if (i < MIDm) { g_s2[i]=0.0; g_ss2[i]=0.0; }
    }

    for (int i = tid; i < 64*64; i += 256) {
        int c = i >> 6, cp = i & 63;
        w1t[cp*68 + c] = w1[c*67 + 3 + cp];
    }
    for (int i = tid; i < 64*32; i += 256) {
        int cp = i >> 5, nl = i & 31;
        fs[i] = f[(b*64 + cp)*2048 + n0 + nl];
    }
    __syncthreads();

    int nl = tid & 31, cg = tid >> 5;
    float acc[8];
    #pragma unroll
    for (int i = 0; i < 8; i++) acc[i] = 0.f;

    #pragma unroll 8
    for (int cp = 0; cp < 64; cp++) {
        float fv = fs[cp*32 + nl];
        float4 wa = *(const float4*)&w1t[cp*68 + cg*8];
        float4 wb = *(const float4*)&w1t[cp*68 + cg*8 + 4];
        acc[0] = fmaf(wa.x, fv, acc[0]);
        acc[1] = fmaf(wa.y, fv, acc[1]);
        acc[2] = fmaf(wa.z, fv, acc[2]);
        acc[3] = fmaf(wa.w, fv, acc[3]);
        acc[4] = fmaf(wb.x, fv, acc[4]);
        acc[5] = fmaf(wb.y, fv, acc[5]);
        acc[6] = fmaf(wb.z, fv, acc[6]);
        acc[7] = fmaf(wb.w, fv, acc[7]);
    }
    #pragma unroll
    for (int i = 0; i < 8; i++) gs[nl*68 + cg*8 + i] = acc[i];
    __syncthreads();
    for (int i = tid; i < 2048; i += 256) {
        int nn = i >> 6, c = i & 63;
        g_feat[(b*2048 + n0 + nn)*64 + c] = gs[nn*68 + c];
    }
}

// ---------------- K_ballq: 32 points per block ----------------
__global__ void __launch_bounds__(1024) k_ballq(const float* __restrict__ p) {
    __shared__ float px[2048], py[2048], pz[2048];
    __shared__ int   ob[32][16];
    int tid = threadIdx.x;
    int b  = blockIdx.x >> 6;
    int n0 = (blockIdx.x & 63) << 5;

    for (int i = tid; i < 2048; i += 1024) {
        const float* pp = p + (size_t)(b*2048 + i)*3;
        px[i] = pp[0]; py[i] = pp[1]; pz[i] = pp[2];
    }
    __syncthreads();

    int w = tid >> 5, lane = tid & 31;
    int n = n0 + w;
    float qx = px[n], qy = py[n], qz = pz[n];
    int cnt = 0;
    for (int j0 = 0; j0 < 2048; j0 += 32) {
        int j = j0 + lane;
        float dx = __fsub_rn(px[j], qx);
        float dy = __fsub_rn(py[j], qy);
        float dz = __fsub_rn(pz[j], qz);
        float d2 = __fadd_rn(__fadd_rn(__fmul_rn(dx,dx), __fmul_rn(dy,dy)), __fmul_rn(dz,dz));
        bool q = d2 < R2c;
        unsigned mask = __ballot_sync(0xffffffffu, q);
        if (mask) {
            int r = cnt + __popc(mask & ((1u << lane) - 1u));
            if (q && r < 16) ob[w][r] = j;
            cnt += __popc(mask);
            if (cnt >= 16) break;
        }
    }
    __syncwarp();
    if (cnt < 16) {
        int first = ob[w][0];
        if (lane >= cnt && lane < 16) ob[w][lane] = first;
        __syncwarp();
    }
    if (lane < 16) g_idx[(b*2048 + n)*16 + lane] = ob[w][lane];
}

// ---------------- K_agg ----------------
__global__ void __launch_bounds__(256) k_agg(const float* __restrict__ p,
                                             const float* __restrict__ w1) {
    __shared__ float ms[64*8];
    __shared__ float s1s[64], q1s[64];
    int tid = threadIdx.x;
    if (tid < 64) { s1s[tid] = 0.f; q1s[tid] = 0.f; }
    __syncthreads();

    int b  = blockIdx.x >> 8;
    int n0 = (blockIdx.x & 255) << 3;
    int w = tid >> 5, lane = tid & 31;
    int n = n0 + w;
    int c0 = lane * 2;

    float wx0 = w1[c0*67+0],     wy0 = w1[c0*67+1],     wz0 = w1[c0*67+2];
    float wx1 = w1[(c0+1)*67+0], wy1 = w1[(c0+1)*67+1], wz1 = w1[(c0+1)*67+2];
    const float* pc = p + (size_t)(b*2048 + n)*3;
    float cx = pc[0], cy = pc[1], cz = pc[2];
    int jr = g_idx[(b*2048 + n)*16 + (lane & 15)];

    float dxr = 0.f, dyr = 0.f, dzr = 0.f;
    if (lane < 16) {
        const float* pj = p + (size_t)(b*2048 + jr)*3;
        dxr = pj[0] - cx; dyr = pj[1] - cy; dzr = pj[2] - cz;
    }

    int js[16];
    #pragma unroll
    for (int k = 0; k < 16; k++) js[k] = __shfl_sync(0xffffffffu, jr, k);

    float2 gv[16];
    #pragma unroll
    for (int k = 0; k < 16; k++)
        gv[k] = __ldg((const float2*)(g_feat + (size_t)(b*2048 + js[k])*64 + c0));

    float mx0 = -3.402823466e38f, mx1 = -3.402823466e38f;
    float s0 = 0.f, q0 = 0.f, s1v = 0.f, q1v = 0.f;
    #pragma unroll
    for (int k = 0; k < 16; k++) {
        float dx = __shfl_sync(0xffffffffu, dxr, k);
        float dy = __shfl_sync(0xffffffffu, dyr, k);
        float dz = __shfl_sync(0xffffffffu, dzr, k);
        float v0 = fmaf(wx0, dx, fmaf(wy0, dy, fmaf(wz0, dz, gv[k].x)));
        float v1 = fmaf(wx1, dx, fmaf(wy1, dy, fmaf(wz1, dz, gv[k].y)));
        mx0 = fmaxf(mx0, v0); mx1 = fmaxf(mx1, v1);
        s0 += v0;  q0  = fmaf(v0, v0, q0);
        s1v += v1; q1v = fmaf(v1, v1, q1v);
    }
    ms[c0*8 + w]     = mx0;
    ms[(c0+1)*8 + w] = mx1;
    atomicAdd(&s1s[c0],   s0);  atomicAdd(&q1s[c0],   q0);
    atomicAdd(&s1s[c0+1], s1v); atomicAdd(&q1s[c0+1], q1v);
    __syncthreads();
    for (int i = tid; i < 512; i += 256) {
        int c = i >> 3, nl = i & 7;
        g_m[(b*64 + c)*2048 + n0 + nl] = ms[i];
    }
    if (tid < 64) {
        atomicAdd(&g_s1[tid],  (double)s1s[tid]);
        atomicAdd(&g_ss1[tid], (double)q1s[tid]);
    }
}

// ---------------- K_mlp1 (HMMA): y[c0..c0+128, n0..n0+64] = w2 @ relu(bn1(m)) ----------------
// block = 128c x 64n, 8 warps of 32c x 32n. grid = 512. A fragments direct from
// global (L1-resident weights); smem holds only B + bn params -> 4 blocks/SM.
// smem: sc@0[256] sh@256[256] s2s@512[512] q2s@1024[512]
//   B_hi@2048 (64x72 bf16 = 9216)  B_lo@11264 (9216)  total 20480
#define M1_BH 2048
#define M1_BL 11264
#define M1_SMEM 20480
#define LDB1 72
__global__ void __launch_bounds__(256, 4) k_mlp1(const float* __restrict__ g1,
                                                 const float* __restrict__ b1) {
    extern __shared__ __align__(16) char smem[];
    uint32_t sb = smem_u32(smem);
    float* sc  = (float*)(smem);
    float* sh  = (float*)(smem + 256);
    float* s2s = (float*)(smem + 512);
    float* q2s = (float*)(smem + 1024);
    int tid = threadIdx.x, wid = tid >> 5, lane = tid & 31;
    int b  = blockIdx.x >> 6;
    int ct = (blockIdx.x >> 5) & 1;
    int nt = blockIdx.x & 31;
    int c0 = ct << 7, n0 = nt << 6;
    int c_w = (wid & 3) << 5, n_w = (wid >> 2) << 5;

    // prefetch B (g_m) while computing bn params
    float2 pb[8];
    #pragma unroll
    for (int j = 0; j < 8; j++) {
        int i = tid + j*256;
        int k = i >> 5, np = i & 31;
        pb[j] = *(const float2*)&g_m[(b*64 + k)*2048 + n0 + np*2];
    }

    if (tid < 64) {
        double cnt = (double)(Bb*Nn*KK);
        double mu  = g_s1[tid] / cnt;
        double var = g_ss1[tid] / cnt - mu*mu;
        float s = g1[tid] * rsqrtf((float)var + EPSc);
        sc[tid] = s;
        sh[tid] = b1[tid] - (float)mu * s;
    }
    if (tid < 128) { s2s[tid] = 0.f; q2s[tid] = 0.f; }
    __syncthreads();

    #pragma unroll
    for (int j = 0; j < 8; j++) {
        int i = tid + j*256;
        int k = i >> 5, np = i & 31;
        float sck = sc[k], shk = sh[k];
        float va = fmaxf(0.f, fmaf(pb[j].x, sck, shk));
        float vb = fmaxf(0.f, fmaf(pb[j].y, sck, shk));
        __nv_bfloat16 ha, la, hb, lb;
        split_bf16(va, ha, la);
        split_bf16(vb, hb, lb);
        *(uint32_t*)(smem + M1_BH + k*(LDB1*2) + np*4) = pack2(ha, hb);
        *(uint32_t*)(smem + M1_BL + k*(LDB1*2) + np*4) = pack2(la, lb);
    }
    __syncthreads();

    float acc[2][4][4];
    #pragma unroll
    for (int i = 0; i < 2; i++)
        #pragma unroll
        for (int j = 0; j < 4; j++)
            #pragma unroll
            for (int r = 0; r < 4; r++) acc[i][j][r] = 0.f;

    int g  = lane >> 2;
    int kb0 = (lane & 3) << 1;
    uint32_t brow = lane & 15;
    #pragma unroll
    for (int ks = 0; ks < 4; ks++) {
        uint32_t bh[4][2], bl[4][2];
        #pragma unroll
        for (int ntl = 0; ntl < 4; ntl++) {
            uint32_t baddr = (ks*16 + brow)*(LDB1*2) + (n_w + ntl*8)*2;
            ldmB(bh[ntl], sb + M1_BH + baddr);
            ldmB(bl[ntl], sb + M1_BL + baddr);
        }
        int kb = ks*16 + kb0;
        #pragma unroll
        for (int mt = 0; mt < 2; mt++) {
            int r = c0 + c_w + mt*16;
            uint32_t ah[4], al[4];
            ldA_frag(ah, g_w2h, 64, r, g, kb);
            ldA_frag(al, g_w2l, 64, r, g, kb);
            #pragma unroll
            for (int ntl = 0; ntl < 4; ntl++) {
                mma16816(acc[mt][ntl], ah, bh[ntl]);
                mma16816(acc[mt][ntl], ah, bl[ntl]);
                mma16816(acc[mt][ntl], al, bh[ntl]);
            }
        }
    }

    int tcol = (lane & 3) * 2;
    #pragma unroll
    for (int mt = 0; mt < 2; mt++) {
        int r0 = c_w + mt*16 + g, r1 = r0 + 8;
        float s0 = 0.f, q0 = 0.f, s1v = 0.f, q1v = 0.f;
        #pragma unroll
        for (int ntl = 0; ntl < 4; ntl++) {
            float d0 = acc[mt][ntl][0], d1 = acc[mt][ntl][1];
            float d2 = acc[mt][ntl][2], d3 = acc[mt][ntl][3];
            int col = n_w + ntl*8 + tcol;
            *(float2*)&g_y[(size_t)(b*256 + c0 + r0)*2048 + n0 + col] = make_float2(d0, d1);
            *(float2*)&g_y[(size_t)(b*256 + c0 + r1)*2048 + n0 + col] = make_float2(d2, d3);
            s0 += d0 + d1; q0 = fmaf(d0, d0, fmaf(d1, d1, q0));
            s1v += d2 + d3; q1v = fmaf(d2, d2, fmaf(d3, d3, q1v));
        }
        atomicAdd(&s2s[r0], s0);  atomicAdd(&q2s[r0], q0);
        atomicAdd(&s2s[r1], s1v); atomicAdd(&q2s[r1], q1v);
    }
    __syncthreads();
    if (tid < 128) {
        atomicAdd(&g_s2[c0 + tid],  (double)s2s[tid]);
        atomicAdd(&g_ss2[c0 + tid], (double)q2s[tid]);
    }
}

// ---------------- K_mlp2 (HMMA): z[64c, n0..n0+64] = w3 @ relu(bn2(y)) ----------------
// block = 64c x 64n, 8 warps of 16c x 32n. grid = 256. A direct from global.
// smem: sc@0[1024] sh@1024[1024] s3s@2048[256] q3s@2304[256]
//   B_hi@2560 (64x72 = 9216)  B_lo@11776 (9216)  total 20992
#define M2_BH 2560
#define M2_BL 11776
#define M2_SMEM 20992
#define LDB2 72
__global__ void __launch_bounds__(256, 4) k_mlp2(const float* __restrict__ g2,
                                                 const float* __restrict__ b2) {
    extern __shared__ __align__(16) char smem[];
    uint32_t sb = smem_u32(smem);
    float* sc  = (float*)(smem);
    float* sh  = (float*)(smem + 1024);
    float* s3s = (float*)(smem + 2048);
    float* q3s = (float*)(smem + 2304);
    int tid = threadIdx.x, wid = tid >> 5, lane = tid & 31;
    int b  = blockIdx.x >> 5;
    int n0 = (blockIdx.x & 31) << 6;
    int c_w = (wid & 3) << 4;   // 0,16,32,48
    int n_w = (wid >> 2) << 5;  // 0,32

    {
        double cnt = (double)(Bb*Nn);
        double mu  = g_s2[tid] / cnt;
        double var = g_ss2[tid] / cnt - mu*mu;
        float s = g2[tid] * rsqrtf((float)var + EPSc);
        sc[tid] = s;
        sh[tid] = b2[tid] - (float)mu * s;
    }
    if (tid < 64) { s3s[tid] = 0.f; q3s[tid] = 0.f; }
    __syncthreads();

    float acc[4][4];
    #pragma unroll
    for (int i = 0; i < 4; i++)
        #pragma unroll
        for (int r = 0; r < 4; r++) acc[i][r] = 0.f;

    int g  = lane >> 2;
    int kb0 = (lane & 3) << 1;
    uint32_t brow = lane & 15;

    for (int q = 0; q < 4; q++) {           // K chunks of 64
        int k0 = q << 6;
        // prefetch B chunk
        float2 pbv[8];
        #pragma unroll
        for (int j = 0; j < 8; j++) {
            int i = tid + j*256;
            int k = i >> 5, np = i & 31;
            pbv[j] = *(const float2*)&g_y[(size_t)(b*256 + k0 + k)*2048 + n0 + np*2];
        }
        #pragma unroll
        for (int j = 0; j < 8; j++) {
            int i = tid + j*256;
            int k = i >> 5, np = i & 31;
            int ch = k0 + k;
            float sck = sc[ch], shk = sh[ch];
            float va = fmaxf(0.f, fmaf(pbv[j].x, sck, shk));
            float vb = fmaxf(0.f, fmaf(pbv[j].y, sck, shk));
            __nv_bfloat16 ha, la, hb, lb;
            split_bf16(va, ha, la);
            split_bf16(vb, hb, lb);
            *(uint32_t*)(smem + M2_BH + k*(LDB2*2) + np*4) = pack2(ha, hb);
            *(uint32_t*)(smem + M2_BL + k*(LDB2*2) + np*4) = pack2(la, lb);
        }
        __syncthreads();

        #pragma unroll
        for (int ks = 0; ks < 4; ks++) {
            uint32_t bh[4][2], bl[4][2];
            #pragma unroll
            for (int ntl = 0; ntl < 4; ntl++) {
                uint32_t baddr = (ks*16 + brow)*(LDB2*2) + (n_w + ntl*8)*2;
                ldmB(bh[ntl], sb + M2_BH + baddr);
                ldmB(bl[ntl], sb + M2_BL + baddr);
            }
            int kb = k0 + ks*16 + kb0;
            uint32_t ah[4], al[4];
            ldA_frag(ah, g_w3h, 256, c_w, g, kb);
            ldA_frag(al, g_w3l, 256, c_w, g, kb);
            #pragma unroll
            for (int ntl = 0; ntl < 4; ntl++) {
                mma16816(acc[ntl], ah, bh[ntl]);
                mma16816(acc[ntl], ah, bl[ntl]);
                mma16816(acc[ntl], al, bh[ntl]);
            }
        }
        __syncthreads();
    }

    int tcol = (lane & 3) * 2;
    {
        int r0 = c_w + g, r1 = r0 + 8;
        float s0 = 0.f, q0 = 0.f, s1v = 0.f, q1v = 0.f;
        #pragma unroll
        for (int ntl = 0; ntl < 4; ntl++) {
            float d0 = acc[ntl][0], d1 = acc[ntl][1];
            float d2 = acc[ntl][2], d3 = acc[ntl][3];
            int col = n_w + ntl*8 + tcol;
            *(float2*)&g_z[(size_t)(b*64 + r0)*2048 + n0 + col] = make_float2(d0, d1);
            *(float2*)&g_z[(size_t)(b*64 + r1)*2048 + n0 + col] = make_float2(d2, d3);
            s0 += d0 + d1; q0 = fmaf(d0, d0, fmaf(d1, d1, q0));
            s1v += d2 + d3; q1v = fmaf(d2, d2, fmaf(d3, d3, q1v));
        }
        atomicAdd(&s3s[r0], s0);  atomicAdd(&q3s[r0], q0);
        atomicAdd(&s3s[r1], s1v); atomicAdd(&q3s[r1], q1v);
    }
    __syncthreads();
    if (tid < 64) {
        atomicAdd(&g_s3[tid],  (double)s3s[tid]);
        atomicAdd(&g_ss3[tid], (double)q3s[tid]);
    }
}

// ---------------- K_out: relu(bn3(z) + f) ----------------
__global__ void __launch_bounds__(256) k_out(const float* __restrict__ f,
                                             const float* __restrict__ g3,
                                             const float* __restrict__ b3,
                                             float* __restrict__ out) {
    __shared__ float sc[64], sh[64];
    int tid = threadIdx.x;
    if (tid < 64) {
        double cnt = (double)(Bb*Nn);
        double mu  = g_s3[tid] / cnt;
        double var = g_ss3[tid] / cnt - mu*mu;
        float s = g3[tid] * rsqrtf((float)var + EPSc);
        sc[tid] = s;
        sh[tid] = b3[tid] - (float)mu * s;
    }
    __syncthreads();
    int i = blockIdx.x * 256 + tid;
    int base = i * 4;
    int c = (base >> 11) & 63;
    float4 z  = *(const float4*)&g_z[base];
    float4 fv = *(const float4*)&f[base];
    float4 o;
    o.x = fmaxf(0.f, fmaf(z.x, sc[c], sh[c]) + fv.x);
    o.y = fmaxf(0.f, fmaf(z.y, sc[c], sh[c]) + fv.y);
    o.z = fmaxf(0.f, fmaf(z.z, sc[c], sh[c]) + fv.z);
    o.w = fmaxf(0.f, fmaf(z.w, sc[c], sh[c]) + fv.w);
    *(float4*)&out[base] = o;
}

// ---------------- launch ----------------
extern "C" void kernel_launch(void* const* d_in, const int* in_sizes, int n_in,
                              void* d_out, int out_size) {
    const float* p  = (const float*)d_in[0];
    const float* f  = (const float*)d_in[1];
    const float* w1 = (const float*)d_in[2];
    const float* g1 = (const float*)d_in[3];
    const float* b1 = (const float*)d_in[4];
    const float* w2 = (const float*)d_in[5];
    const float* g2 = (const float*)d_in[6];
    const float* b2 = (const float*)d_in[7];
    const float* w3 = (const float*)d_in[8];
    const float* g3 = (const float*)d_in[9];
    const float* b3 = (const float*)d_in[10];
    float* out = (float*)d_out;

    cudaFuncSetAttribute(k_mlp1, cudaFuncAttributeMaxDynamicSharedMemorySize, M1_SMEM);
    cudaFuncSetAttribute(k_mlp2, cudaFuncAttributeMaxDynamicSharedMemorySize, M2_SMEM);

    k_gfeat<<<512,  256>>>(f, w1, w2, w3);
    k_ballq<<<512, 1024>>>(p);
    k_agg  <<<2048, 256>>>(p, w1);
    k_mlp1 <<<512,  256, M1_SMEM>>>(g1, b1);
    k_mlp2 <<<256,  256, M2_SMEM>>>(g2, b2);
    k_out  <<<1024, 256>>>(f, g3, b3, out);
}

// round 12
// speedup vs baseline: 1.0758x; 1.0758x over previous
#include <cuda_runtime.h>
#include <cuda_bf16.h>
#include <cstdint>

#define Bb   8
#define Nn   2048
#define Cc   64
#define MIDm 256
#define KK   16
#define R2c  0.0225f
#define EPSc 1e-5f

// ---------------- scratch (device globals, no allocation) ----------------
__device__ __align__(16) int    g_idx[Bb*Nn*KK];      // [b][n][16]
__device__ __align__(16) float  g_feat[Bb*Nn*Cc];     // [b][n][c]  = w1[:,3:]@f
__device__ __align__(16) float  g_m[Bb*Cc*Nn];        // [b][c][n]  = max_k x
__device__ __align__(16) float  g_y[Bb*MIDm*Nn];      // [b][c][n]
__device__ __align__(16) float  g_z[Bb*Cc*Nn];        // [b][c][n]
// split-bf16 weights (same layout as source, no transpose needed)
__device__ __align__(16) __nv_bfloat16 g_w2h[MIDm*Cc], g_w2l[MIDm*Cc];   // [o=256][k=64]
__device__ __align__(16) __nv_bfloat16 g_w3h[Cc*MIDm], g_w3l[Cc*MIDm];   // [c=64][k=256]
__device__ double g_s1[Cc],   g_ss1[Cc];
__device__ double g_s2[MIDm], g_ss2[MIDm];
__device__ double g_s3[Cc],   g_ss3[Cc];

// ---------------- mma/ldmatrix helpers ----------------
__device__ __forceinline__ uint32_t smem_u32(const void* p) {
    uint32_t r;
    asm("{ .reg .u64 t; cvta.to.shared.u64 t, %1; cvt.u32.u64 %0, t; }" : "=r"(r) : "l"(p));
    return r;
}
__device__ __forceinline__ void ldmA(uint32_t* a, uint32_t addr) {   // x4 non-trans
    asm volatile("ldmatrix.sync.aligned.m8n8.x4.shared.b16 {%0,%1,%2,%3}, [%4];"
                 : "=r"(a[0]), "=r"(a[1]), "=r"(a[2]), "=r"(a[3]) : "r"(addr));
}
__device__ __forceinline__ void ldmB(uint32_t* b2, uint32_t addr) {  // x2 trans
    asm volatile("ldmatrix.sync.aligned.m8n8.x2.trans.shared.b16 {%0,%1}, [%2];"
                 : "=r"(b2[0]), "=r"(b2[1]) : "r"(addr));
}
__device__ __forceinline__ void mma16816(float* d, const uint32_t* a, const uint32_t* b2) {
    asm volatile(
        "mma.sync.aligned.m16n8k16.row.col.f32.bf16.bf16.f32 "
        "{%0,%1,%2,%3}, {%4,%5,%6,%7}, {%8,%9}, {%0,%1,%2,%3};"
        : "+f"(d[0]), "+f"(d[1]), "+f"(d[2]), "+f"(d[3])
        : "r"(a[0]), "r"(a[1]), "r"(a[2]), "r"(a[3]), "r"(b2[0]), "r"(b2[1]));
}
__device__ __forceinline__ void split_bf16(float v, __nv_bfloat16& h, __nv_bfloat16& l) {
    h = __float2bfloat16_rn(v);
    l = __float2bfloat16_rn(v - __bfloat162float(h));
}
__device__ __forceinline__ uint32_t pack2(__nv_bfloat16 a, __nv_bfloat16 b) {
    return (uint32_t)__bfloat16_as_ushort(a) | ((uint32_t)__bfloat16_as_ushort(b) << 16);
}

// ---------------- K_gfeat (+prep in blocks<64) ----------------
__global__ void __launch_bounds__(256) k_gfeat(const float* __restrict__ f,
                                               const float* __restrict__ w1,
                                               const float* __restrict__ w2,
                                               const float* __restrict__ w3) {
    __shared__ __align__(16) float w1t[64*68];
    __shared__ __align__(16) float fs[64*32];
    __shared__ __align__(16) float gs[32*68];
    int tid = threadIdx.x;
    int b  = blockIdx.x >> 6;
    int n0 = (blockIdx.x & 63) << 5;

    if (blockIdx.x < 64) {
        int i = blockIdx.x * 256 + tid;          // 0..16383
        { __nv_bfloat16 h, l; split_bf16(w2[i], h, l); g_w2h[i] = h; g_w2l[i] = l; }
        { __nv_bfloat16 h, l; split_bf16(w3[i], h, l); g_w3h[i] = h; g_w3l[i] = l; }
        if (i < Cc)   { g_s1[i]=0.0; g_ss1[i]=0.0; g_s3[i]=0.0; g_ss3[i]=0.0; }
        if (i < MIDm) { g_s2[i]=0.0; g_ss2[i]=0.0; }
    }

    for (int i = tid; i < 64*64; i += 256) {
        int c = i >> 6, cp = i & 63;
        w1t[cp*68 + c] = w1[c*67 + 3 + cp];
    }
    for (int i = tid; i < 64*32; i += 256) {
        int cp = i >> 5, nl = i & 31;
        fs[i] = f[(b*64 + cp)*2048 + n0 + nl];
    }
    __syncthreads();

    int nl = tid & 31, cg = tid >> 5;
    float acc[8];
    #pragma unroll
    for (int i = 0; i < 8; i++) acc[i] = 0.f;

    #pragma unroll 8
    for (int cp = 0; cp < 64; cp++) {
        float fv = fs[cp*32 + nl];
        float4 wa = *(const float4*)&w1t[cp*68 + cg*8];
        float4 wb = *(const float4*)&w1t[cp*68 + cg*8 + 4];
        acc[0] = fmaf(wa.x, fv, acc[0]);
        acc[1] = fmaf(wa.y, fv, acc[1]);
        acc[2] = fmaf(wa.z, fv, acc[2]);
        acc[3] = fmaf(wa.w, fv, acc[3]);
        acc[4] = fmaf(wb.x, fv, acc[4]);
        acc[5] = fmaf(wb.y, fv, acc[5]);
        acc[6] = fmaf(wb.z, fv, acc[6]);
        acc[7] = fmaf(wb.w, fv, acc[7]);
    }
    #pragma unroll
    for (int i = 0; i < 8; i++) gs[nl*68 + cg*8 + i] = acc[i];
    __syncthreads();
    for (int i = tid; i < 2048; i += 256) {
        int nn = i >> 6, c = i & 63;
        g_feat[(b*2048 + n0 + nn)*64 + c] = gs[nn*68 + c];
    }
}

// ---------------- K_ballq: 32 points per block ----------------
__global__ void __launch_bounds__(1024) k_ballq(const float* __restrict__ p) {
    __shared__ float px[2048], py[2048], pz[2048];
    __shared__ int   ob[32][16];
    int tid = threadIdx.x;
    int b  = blockIdx.x >> 6;
    int n0 = (blockIdx.x & 63) << 5;

    for (int i = tid; i < 2048; i += 1024) {
        const float* pp = p + (size_t)(b*2048 + i)*3;
        px[i] = pp[0]; py[i] = pp[1]; pz[i] = pp[2];
    }
    __syncthreads();

    int w = tid >> 5, lane = tid & 31;
    int n = n0 + w;
    float qx = px[n], qy = py[n], qz = pz[n];
    int cnt = 0;
    for (int j0 = 0; j0 < 2048; j0 += 32) {
        int j = j0 + lane;
        float dx = __fsub_rn(px[j], qx);
        float dy = __fsub_rn(py[j], qy);
        float dz = __fsub_rn(pz[j], qz);
        float d2 = __fadd_rn(__fadd_rn(__fmul_rn(dx,dx), __fmul_rn(dy,dy)), __fmul_rn(dz,dz));
        bool q = d2 < R2c;
        unsigned mask = __ballot_sync(0xffffffffu, q);
        if (mask) {
            int r = cnt + __popc(mask & ((1u << lane) - 1u));
            if (q && r < 16) ob[w][r] = j;
            cnt += __popc(mask);
            if (cnt >= 16) break;
        }
    }
    __syncwarp();
    if (cnt < 16) {
        int first = ob[w][0];
        if (lane >= cnt && lane < 16) ob[w][lane] = first;
        __syncwarp();
    }
    if (lane < 16) g_idx[(b*2048 + n)*16 + lane] = ob[w][lane];
}

// ---------------- K_agg: x = g[j] + w1p@dp ; stats1 + max over K ----------------
// Warp per point. dp broadcast via smem LDS.128 (replaces 48 SHFL/lane).
__global__ void __launch_bounds__(256) k_agg(const float* __restrict__ p,
                                             const float* __restrict__ w1) {
    __shared__ float ms[64*8];
    __shared__ __align__(16) float dps[8][16][4];
    __shared__ float s1s[64], q1s[64];
    int tid = threadIdx.x;
    if (tid < 64) { s1s[tid] = 0.f; q1s[tid] = 0.f; }
    __syncthreads();

    int b  = blockIdx.x >> 8;
    int n0 = (blockIdx.x & 255) << 3;
    int w = tid >> 5, lane = tid & 31;
    int n = n0 + w;
    int c0 = lane * 2;

    float wx0 = w1[c0*67+0],     wy0 = w1[c0*67+1],     wz0 = w1[c0*67+2];
    float wx1 = w1[(c0+1)*67+0], wy1 = w1[(c0+1)*67+1], wz1 = w1[(c0+1)*67+2];
    const float* pc = p + (size_t)(b*2048 + n)*3;
    float cx = pc[0], cy = pc[1], cz = pc[2];
    int jr = g_idx[(b*2048 + n)*16 + (lane & 15)];

    // lanes 0-15 fetch their neighbor's coords and write dp to smem
    if (lane < 16) {
        const float* pj = p + (size_t)(b*2048 + jr)*3;
        dps[w][lane][0] = pj[0] - cx;
        dps[w][lane][1] = pj[1] - cy;
        dps[w][lane][2] = pj[2] - cz;
    }

    int js[16];
    #pragma unroll
    for (int k = 0; k < 16; k++) js[k] = __shfl_sync(0xffffffffu, jr, k);

    // batched gather: 16 independent float2 loads in flight
    float2 gv[16];
    #pragma unroll
    for (int k = 0; k < 16; k++)
        gv[k] = __ldg((const float2*)(g_feat + (size_t)(b*2048 + js[k])*64 + c0));

    __syncwarp();

    float mx0 = -3.402823466e38f, mx1 = -3.402823466e38f;
    float s0 = 0.f, q0 = 0.f, s1v = 0.f, q1v = 0.f;
    #pragma unroll
    for (int k = 0; k < 16; k++) {
        float4 d = *(const float4*)&dps[w][k][0];   // broadcast, conflict-free
        float v0 = fmaf(wx0, d.x, fmaf(wy0, d.y, fmaf(wz0, d.z, gv[k].x)));
        float v1 = fmaf(wx1, d.x, fmaf(wy1, d.y, fmaf(wz1, d.z, gv[k].y)));
        mx0 = fmaxf(mx0, v0); mx1 = fmaxf(mx1, v1);
        s0 += v0;  q0  = fmaf(v0, v0, q0);
        s1v += v1; q1v = fmaf(v1, v1, q1v);
    }
    ms[c0*8 + w]     = mx0;
    ms[(c0+1)*8 + w] = mx1;
    atomicAdd(&s1s[c0],   s0);  atomicAdd(&q1s[c0],   q0);
    atomicAdd(&s1s[c0+1], s1v); atomicAdd(&q1s[c0+1], q1v);
    __syncthreads();
    for (int i = tid; i < 512; i += 256) {
        int c = i >> 3, nl = i & 7;
        g_m[(b*64 + c)*2048 + n0 + nl] = ms[i];
    }
    if (tid < 64) {
        atomicAdd(&g_s1[tid],  (double)s1s[tid]);
        atomicAdd(&g_ss1[tid], (double)q1s[tid]);
    }
}

// ---------------- K_mlp1 (HMMA): y[c0..c0+128, n0..n0+64] = w2 @ relu(bn1(m)) ----------------
// block = 128c x 64n, 8 warps of 32c x 32n. grid = 512. (R9 proven version)
#define M1_AH 2048
#define M1_AL 20480
#define M1_BH 38912
#define M1_BL 48128
#define M1_SMEM 57344
#define LDA1 72
#define LDB1 72
__global__ void __launch_bounds__(256) k_mlp1(const float* __restrict__ g1,
                                              const float* __restrict__ b1) {
    extern __shared__ __align__(16) char smem[];
    uint32_t sb = smem_u32(smem);
    float* sc  = (float*)(smem);
    float* sh  = (float*)(smem + 256);
    float* s2s = (float*)(smem + 512);
    float* q2s = (float*)(smem + 1024);
    int tid = threadIdx.x, wid = tid >> 5, lane = tid & 31;
    int b  = blockIdx.x >> 6;
    int ct = (blockIdx.x >> 5) & 1;
    int nt = blockIdx.x & 31;
    int c0 = ct << 7, n0 = nt << 6;
    int c_w = (wid & 3) << 5, n_w = (wid >> 2) << 5;

    // prefetch A (weights) and B (g_m) while computing bn params
    uint4 pa_h[4], pa_l[4];
    #pragma unroll
    for (int j = 0; j < 4; j++) {
        int i = tid + j*256;
        int row = i >> 3, c8 = i & 7;
        pa_h[j] = ((const uint4*)(g_w2h + (size_t)(c0 + row)*64))[c8];
        pa_l[j] = ((const uint4*)(g_w2l + (size_t)(c0 + row)*64))[c8];
    }
    float2 pb[8];
    #pragma unroll
    for (int j = 0; j < 8; j++) {
        int i = tid + j*256;
        int k = i >> 5, np = i & 31;
        pb[j] = *(const float2*)&g_m[(b*64 + k)*2048 + n0 + np*2];
    }

    if (tid < 64) {
        double cnt = (double)(Bb*Nn*KK);
        double mu  = g_s1[tid] / cnt;
        double var = g_ss1[tid] / cnt - mu*mu;
        float s = g1[tid] * rsqrtf((float)var + EPSc);
        sc[tid] = s;
        sh[tid] = b1[tid] - (float)mu * s;
    }
    if (tid < 128) { s2s[tid] = 0.f; q2s[tid] = 0.f; }
    __syncthreads();

    #pragma unroll
    for (int j = 0; j < 4; j++) {
        int i = tid + j*256;
        int row = i >> 3, c8 = i & 7;
        *(uint4*)(smem + M1_AH + row*(LDA1*2) + c8*16) = pa_h[j];
        *(uint4*)(smem + M1_AL + row*(LDA1*2) + c8*16) = pa_l[j];
    }
    #pragma unroll
    for (int j = 0; j < 8; j++) {
        int i = tid + j*256;
        int k = i >> 5, np = i & 31;
        float sck = sc[k], shk = sh[k];
        float va = fmaxf(0.f, fmaf(pb[j].x, sck, shk));
        float vb = fmaxf(0.f, fmaf(pb[j].y, sck, shk));
        __nv_bfloat16 ha, la, hb, lb;
        split_bf16(va, ha, la);
        split_bf16(vb, hb, lb);
        *(uint32_t*)(smem + M1_BH + k*(LDB1*2) + np*4) = pack2(ha, hb);
        *(uint32_t*)(smem + M1_BL + k*(LDB1*2) + np*4) = pack2(la, lb);
    }
    __syncthreads();

    float acc[2][4][4];
    #pragma unroll
    for (int i = 0; i < 2; i++)
        #pragma unroll
        for (int j = 0; j < 4; j++)
            #pragma unroll
            for (int r = 0; r < 4; r++) acc[i][j][r] = 0.f;

    uint32_t arow = lane & 15, acol = (lane >> 4) << 3;
    uint32_t brow = lane & 15;
    #pragma unroll
    for (int ks = 0; ks < 4; ks++) {
        uint32_t bh[4][2], bl[4][2];
        #pragma unroll
        for (int ntl = 0; ntl < 4; ntl++) {
            uint32_t baddr = (ks*16 + brow)*(LDB1*2) + (n_w + ntl*8)*2;
            ldmB(bh[ntl], sb + M1_BH + baddr);
            ldmB(bl[ntl], sb + M1_BL + baddr);
        }
        #pragma unroll
        for (int mt = 0; mt < 2; mt++) {
            uint32_t aaddr = (c_w + mt*16 + arow)*(LDA1*2) + (ks*16 + acol)*2;
            uint32_t ah[4], al[4];
            ldmA(ah, sb + M1_AH + aaddr);
            ldmA(al, sb + M1_AL + aaddr);
            #pragma unroll
            for (int ntl = 0; ntl < 4; ntl++) {
                mma16816(acc[mt][ntl], ah, bh[ntl]);
                mma16816(acc[mt][ntl], ah, bl[ntl]);
                mma16816(acc[mt][ntl], al, bh[ntl]);
            }
        }
    }

    int g = lane >> 2, tcol = (lane & 3) * 2;
    #pragma unroll
    for (int mt = 0; mt < 2; mt++) {
        int r0 = c_w + mt*16 + g, r1 = r0 + 8;
        float s0 = 0.f, q0 = 0.f, s1v = 0.f, q1v = 0.f;
        #pragma unroll
        for (int ntl = 0; ntl < 4; ntl++) {
            float d0 = acc[mt][ntl][0], d1 = acc[mt][ntl][1];
            float d2 = acc[mt][ntl][2], d3 = acc[mt][ntl][3];
            int col = n_w + ntl*8 + tcol;
            *(float2*)&g_y[(size_t)(b*256 + c0 + r0)*2048 + n0 + col] = make_float2(d0, d1);
            *(float2*)&g_y[(size_t)(b*256 + c0 + r1)*2048 + n0 + col] = make_float2(d2, d3);
            s0 += d0 + d1; q0 = fmaf(d0, d0, fmaf(d1, d1, q0));
            s1v += d2 + d3; q1v = fmaf(d2, d2, fmaf(d3, d3, q1v));
        }
        atomicAdd(&s2s[r0], s0);  atomicAdd(&q2s[r0], q0);
        atomicAdd(&s2s[r1], s1v); atomicAdd(&q2s[r1], q1v);
    }
    __syncthreads();
    if (tid < 128) {
        atomicAdd(&g_s2[c0 + tid],  (double)s2s[tid]);
        atomicAdd(&g_ss2[c0 + tid], (double)q2s[tid]);
    }
}

// ---------------- K_mlp2 (HMMA): z[64c, n0..n0+64] = w3 @ relu(bn2(y)) ----------------
// block = 64c x 64n, 8 warps of 16c x 32n. grid = 256. (R9 proven version)
#define M2_AH 2560
#define M2_AL 11776
#define M2_BH 20992
#define M2_BL 30208
#define M2_SMEM 39424
#define LDA2 72
#define LDB2 72
__global__ void __launch_bounds__(256) k_mlp2(const float* __restrict__ g2,
                                              const float* __restrict__ b2) {
    extern __shared__ __align__(16) char smem[];
    uint32_t sb = smem_u32(smem);
    float* sc  = (float*)(smem);
    float* sh  = (float*)(smem + 1024);
    float* s3s = (float*)(smem + 2048);
    float* q3s = (float*)(smem + 2304);
    int tid = threadIdx.x, wid = tid >> 5, lane = tid & 31;
    int b  = blockIdx.x >> 5;
    int n0 = (blockIdx.x & 31) << 6;
    int c_w = (wid & 3) << 4;   // 0,16,32,48
    int n_w = (wid >> 2) << 5;  // 0,32

    {
        double cnt = (double)(Bb*Nn);
        double mu  = g_s2[tid] / cnt;
        double var = g_ss2[tid] / cnt - mu*mu;
        float s = g2[tid] * rsqrtf((float)var + EPSc);
        sc[tid] = s;
        sh[tid] = b2[tid] - (float)mu * s;
    }
    if (tid < 64) { s3s[tid] = 0.f; q3s[tid] = 0.f; }
    __syncthreads();

    float acc[4][4];
    #pragma unroll
    for (int i = 0; i < 4; i++)
        #pragma unroll
        for (int r = 0; r < 4; r++) acc[i][r] = 0.f;

    uint32_t arow = lane & 15, acol = (lane >> 4) << 3;
    uint32_t brow = lane & 15;

    for (int q = 0; q < 4; q++) {           // K chunks of 64
        int k0 = q << 6;
        // prefetch chunk
        uint4 pa_h[2], pa_l[2];
        #pragma unroll
        for (int j = 0; j < 2; j++) {
            int i = tid + j*256;
            int row = i >> 3, c8 = i & 7;
            pa_h[j] = ((const uint4*)(g_w3h + (size_t)row*256 + k0))[c8];
            pa_l[j] = ((const uint4*)(g_w3l + (size_t)row*256 + k0))[c8];
        }
        float2 pbv[8];
        #pragma unroll
        for (int j = 0; j < 8; j++) {
            int i = tid + j*256;
            int k = i >> 5, np = i & 31;
            pbv[j] = *(const float2*)&g_y[(size_t)(b*256 + k0 + k)*2048 + n0 + np*2];
        }
        #pragma unroll
        for (int j = 0; j < 2; j++) {
            int i = tid + j*256;
            int row = i >> 3, c8 = i & 7;
            *(uint4*)(smem + M2_AH + row*(LDA2*2) + c8*16) = pa_h[j];
            *(uint4*)(smem + M2_AL + row*(LDA2*2) + c8*16) = pa_l[j];
        }
        #pragma unroll
        for (int j = 0; j < 8; j++) {
            int i = tid + j*256;
            int k = i >> 5, np = i & 31;
            int ch = k0 + k;
            float sck = sc[ch], shk = sh[ch];
            float va = fmaxf(0.f, fmaf(pbv[j].x, sck, shk));
            float vb = fmaxf(0.f, fmaf(pbv[j].y, sck, shk));
            __nv_bfloat16 ha, la, hb, lb;
            split_bf16(va, ha, la);
            split_bf16(vb, hb, lb);
            *(uint32_t*)(smem + M2_BH + k*(LDB2*2) + np*4) = pack2(ha, hb);
            *(uint32_t*)(smem + M2_BL + k*(LDB2*2) + np*4) = pack2(la, lb);
        }
        __syncthreads();

        #pragma unroll
        for (int ks = 0; ks < 4; ks++) {
            uint32_t bh[4][2], bl[4][2];
            #pragma unroll
            for (int ntl = 0; ntl < 4; ntl++) {
                uint32_t baddr = (ks*16 + brow)*(LDB2*2) + (n_w + ntl*8)*2;
                ldmB(bh[ntl], sb + M2_BH + baddr);
                ldmB(bl[ntl], sb + M2_BL + baddr);
            }
            uint32_t aaddr = (c_w + arow)*(LDA2*2) + (ks*16 + acol)*2;
            uint32_t ah[4], al[4];
            ldmA(ah, sb + M2_AH + aaddr);
            ldmA(al, sb + M2_AL + aaddr);
            #pragma unroll
            for (int ntl = 0; ntl < 4; ntl++) {
                mma16816(acc[ntl], ah, bh[ntl]);
                mma16816(acc[ntl], ah, bl[ntl]);
                mma16816(acc[ntl], al, bh[ntl]);
            }
        }
        __syncthreads();
    }

    int g = lane >> 2, tcol = (lane & 3) * 2;
    {
        int r0 = c_w + g, r1 = r0 + 8;
        float s0 = 0.f, q0 = 0.f, s1v = 0.f, q1v = 0.f;
        #pragma unroll
        for (int ntl = 0; ntl < 4; ntl++) {
            float d0 = acc[ntl][0], d1 = acc[ntl][1];
            float d2 = acc[ntl][2], d3 = acc[ntl][3];
            int col = n_w + ntl*8 + tcol;
            *(float2*)&g_z[(size_t)(b*64 + r0)*2048 + n0 + col] = make_float2(d0, d1);
            *(float2*)&g_z[(size_t)(b*64 + r1)*2048 + n0 + col] = make_float2(d2, d3);
            s0 += d0 + d1; q0 = fmaf(d0, d0, fmaf(d1, d1, q0));
            s1v += d2 + d3; q1v = fmaf(d2, d2, fmaf(d3, d3, q1v));
        }
        atomicAdd(&s3s[r0], s0);  atomicAdd(&q3s[r0], q0);
        atomicAdd(&s3s[r1], s1v); atomicAdd(&q3s[r1], q1v);
    }
    __syncthreads();
    if (tid < 64) {
        atomicAdd(&g_s3[tid],  (double)s3s[tid]);
        atomicAdd(&g_ss3[tid], (double)q3s[tid]);
    }
}

// ---------------- K_out: relu(bn3(z) + f) ----------------
__global__ void __launch_bounds__(256) k_out(const float* __restrict__ f,
                                             const float* __restrict__ g3,
                                             const float* __restrict__ b3,
                                             float* __restrict__ out) {
    __shared__ float sc[64], sh[64];
    int tid = threadIdx.x;
    if (tid < 64) {
        double cnt = (double)(Bb*Nn);
        double mu  = g_s3[tid] / cnt;
        double var = g_ss3[tid] / cnt - mu*mu;
        float s = g3[tid] * rsqrtf((float)var + EPSc);
        sc[tid] = s;
        sh[tid] = b3[tid] - (float)mu * s;
    }
    __syncthreads();
    int i = blockIdx.x * 256 + tid;
    int base = i * 4;
    int c = (base >> 11) & 63;
    float4 z  = *(const float4*)&g_z[base];
    float4 fv = *(const float4*)&f[base];
    float4 o;
    o.x = fmaxf(0.f, fmaf(z.x, sc[c], sh[c]) + fv.x);
    o.y = fmaxf(0.f, fmaf(z.y, sc[c], sh[c]) + fv.y);
    o.z = fmaxf(0.f, fmaf(z.z, sc[c], sh[c]) + fv.z);
    o.w = fmaxf(0.f, fmaf(z.w, sc[c], sh[c]) + fv.w);
    *(float4*)&out[base] = o;
}

// ---------------- launch ----------------
extern "C" void kernel_launch(void* const* d_in, const int* in_sizes, int n_in,
                              void* d_out, int out_size) {
    const float* p  = (const float*)d_in[0];
    const float* f  = (const float*)d_in[1];
    const float* w1 = (const float*)d_in[2];
    const float* g1 = (const float*)d_in[3];
    const float* b1 = (const float*)d_in[4];
    const float* w2 = (const float*)d_in[5];
    const float* g2 = (const float*)d_in[6];
    const float* b2 = (const float*)d_in[7];
    const float* w3 = (const float*)d_in[8];
    const float* g3 = (const float*)d_in[9];
    const float* b3 = (const float*)d_in[10];
    float* out = (float*)d_out;

    cudaFuncSetAttribute(k_mlp1, cudaFuncAttributeMaxDynamicSharedMemorySize, M1_SMEM);
    cudaFuncSetAttribute(k_mlp2, cudaFuncAttributeMaxDynamicSharedMemorySize, M2_SMEM);

    k_gfeat<<<512,  256>>>(f, w1, w2, w3);
    k_ballq<<<512, 1024>>>(p);
    k_agg  <<<2048, 256>>>(p, w1);
    k_mlp1 <<<512,  256, M1_SMEM>>>(g1, b1);
    k_mlp2 <<<256,  256, M2_SMEM>>>(g2, b2);
    k_out  <<<1024, 256>>>(f, g3, b3, out);
}

// round 13
// speedup vs baseline: 1.0948x; 1.0177x over previous
#include <cuda_runtime.h>
#include <cuda_bf16.h>
#include <cstdint>

#define Bb   8
#define Nn   2048
#define Cc   64
#define MIDm 256
#define KK   16
#define R2c  0.0225f
#define EPSc 1e-5f

// ---------------- scratch (device globals, no allocation) ----------------
__device__ __align__(16) int    g_idx[Bb*Nn*KK];      // [b][n][16]
__device__ __align__(16) float  g_feat[Bb*Nn*Cc];     // [b][n][c]  = w1[:,3:]@f
__device__ __align__(16) float  g_m[Bb*Cc*Nn];        // [b][c][n]  = max_k x
__device__ __align__(16) float  g_y[Bb*MIDm*Nn];      // [b][c][n]
__device__ __align__(16) float  g_z[Bb*Cc*Nn];        // [b][c][n]
// split-bf16 weights (same layout as source, no transpose needed)
__device__ __align__(16) __nv_bfloat16 g_w2h[MIDm*Cc], g_w2l[MIDm*Cc];   // [o=256][k=64]
__device__ __align__(16) __nv_bfloat16 g_w3h[Cc*MIDm], g_w3l[Cc*MIDm];   // [c=64][k=256]
__device__ double g_s1[Cc],   g_ss1[Cc];
__device__ double g_s2[MIDm], g_ss2[MIDm];
__device__ double g_s3[Cc],   g_ss3[Cc];

// ---------------- mma/ldmatrix helpers ----------------
__device__ __forceinline__ uint32_t smem_u32(const void* p) {
    uint32_t r;
    asm("{ .reg .u64 t; cvta.to.shared.u64 t, %1; cvt.u32.u64 %0, t; }" : "=r"(r) : "l"(p));
    return r;
}
__device__ __forceinline__ void ldmA(uint32_t* a, uint32_t addr) {   // x4 non-trans
    asm volatile("ldmatrix.sync.aligned.m8n8.x4.shared.b16 {%0,%1,%2,%3}, [%4];"
                 : "=r"(a[0]), "=r"(a[1]), "=r"(a[2]), "=r"(a[3]) : "r"(addr));
}
__device__ __forceinline__ void ldmB(uint32_t* b2, uint32_t addr) {  // x2 trans
    asm volatile("ldmatrix.sync.aligned.m8n8.x2.trans.shared.b16 {%0,%1}, [%2];"
                 : "=r"(b2[0]), "=r"(b2[1]) : "r"(addr));
}
__device__ __forceinline__ void mma16816(float* d, const uint32_t* a, const uint32_t* b2) {
    asm volatile(
        "mma.sync.aligned.m16n8k16.row.col.f32.bf16.bf16.f32 "
        "{%0,%1,%2,%3}, {%4,%5,%6,%7}, {%8,%9}, {%0,%1,%2,%3};"
        : "+f"(d[0]), "+f"(d[1]), "+f"(d[2]), "+f"(d[3])
        : "r"(a[0]), "r"(a[1]), "r"(a[2]), "r"(a[3]), "r"(b2[0]), "r"(b2[1]));
}
__device__ __forceinline__ void split_bf16(float v, __nv_bfloat16& h, __nv_bfloat16& l) {
    h = __float2bfloat16_rn(v);
    l = __float2bfloat16_rn(v - __bfloat162float(h));
}
__device__ __forceinline__ uint32_t pack2(__nv_bfloat16 a, __nv_bfloat16 b) {
    return (uint32_t)__bfloat16_as_ushort(a) | ((uint32_t)__bfloat16_as_ushort(b) << 16);
}

// ---------------- K_prep: split-bf16 weights + stat zeroing (launch #1) ----------------
__global__ void __launch_bounds__(256) k_prep(const float* __restrict__ w2,
                                              const float* __restrict__ w3) {
    int i = blockIdx.x * 256 + threadIdx.x;   // 0..16383
    { __nv_bfloat16 h, l; split_bf16(w2[i], h, l); g_w2h[i] = h; g_w2l[i] = l; }
    { __nv_bfloat16 h, l; split_bf16(w3[i], h, l); g_w3h[i] = h; g_w3l[i] = l; }
    if (i < Cc)   { g_s1[i]=0.0; g_ss1[i]=0.0; g_s3[i]=0.0; g_ss3[i]=0.0; }
    if (i < MIDm) { g_s2[i]=0.0; g_ss2[i]=0.0; }
}

// ---------------- K_gfeat ----------------
__global__ void __launch_bounds__(256) k_gfeat(const float* __restrict__ f,
                                               const float* __restrict__ w1) {
    __shared__ __align__(16) float w1t[64*68];
    __shared__ __align__(16) float fs[64*32];
    __shared__ __align__(16) float gs[32*68];
    int tid = threadIdx.x;
    int b  = blockIdx.x >> 6;
    int n0 = (blockIdx.x & 63) << 5;

    for (int i = tid; i < 64*64; i += 256) {
        int c = i >> 6, cp = i & 63;
        w1t[cp*68 + c] = w1[c*67 + 3 + cp];
    }
    for (int i = tid; i < 64*32; i += 256) {
        int cp = i >> 5, nl = i & 31;
        fs[i] = f[(b*64 + cp)*2048 + n0 + nl];
    }
    __syncthreads();

    int nl = tid & 31, cg = tid >> 5;
    float acc[8];
    #pragma unroll
    for (int i = 0; i < 8; i++) acc[i] = 0.f;

    #pragma unroll 8
    for (int cp = 0; cp < 64; cp++) {
        float fv = fs[cp*32 + nl];
        float4 wa = *(const float4*)&w1t[cp*68 + cg*8];
        float4 wb = *(const float4*)&w1t[cp*68 + cg*8 + 4];
        acc[0] = fmaf(wa.x, fv, acc[0]);
        acc[1] = fmaf(wa.y, fv, acc[1]);
        acc[2] = fmaf(wa.z, fv, acc[2]);
        acc[3] = fmaf(wa.w, fv, acc[3]);
        acc[4] = fmaf(wb.x, fv, acc[4]);
        acc[5] = fmaf(wb.y, fv, acc[5]);
        acc[6] = fmaf(wb.z, fv, acc[6]);
        acc[7] = fmaf(wb.w, fv, acc[7]);
    }
    #pragma unroll
    for (int i = 0; i < 8; i++) gs[nl*68 + cg*8 + i] = acc[i];
    __syncthreads();
    for (int i = tid; i < 2048; i += 256) {
        int nn = i >> 6, c = i & 63;
        g_feat[(b*2048 + n0 + nn)*64 + c] = gs[nn*68 + c];
    }
}

// ---------------- K_ballq: 32 points per block ----------------
__global__ void __launch_bounds__(1024) k_ballq(const float* __restrict__ p) {
    __shared__ float px[2048], py[2048], pz[2048];
    __shared__ int   ob[32][16];
    int tid = threadIdx.x;
    int b  = blockIdx.x >> 6;
    int n0 = (blockIdx.x & 63) << 5;

    for (int i = tid; i < 2048; i += 1024) {
        const float* pp = p + (size_t)(b*2048 + i)*3;
        px[i] = pp[0]; py[i] = pp[1]; pz[i] = pp[2];
    }
    __syncthreads();

    int w = tid >> 5, lane = tid & 31;
    int n = n0 + w;
    float qx = px[n], qy = py[n], qz = pz[n];
    int cnt = 0;
    for (int j0 = 0; j0 < 2048; j0 += 32) {
        int j = j0 + lane;
        float dx = __fsub_rn(px[j], qx);
        float dy = __fsub_rn(py[j], qy);
        float dz = __fsub_rn(pz[j], qz);
        float d2 = __fadd_rn(__fadd_rn(__fmul_rn(dx,dx), __fmul_rn(dy,dy)), __fmul_rn(dz,dz));
        bool q = d2 < R2c;
        unsigned mask = __ballot_sync(0xffffffffu, q);
        if (mask) {
            int r = cnt + __popc(mask & ((1u << lane) - 1u));
            if (q && r < 16) ob[w][r] = j;
            cnt += __popc(mask);
            if (cnt >= 16) break;
        }
    }
    __syncwarp();
    if (cnt < 16) {
        int first = ob[w][0];
        if (lane >= cnt && lane < 16) ob[w][lane] = first;
        __syncwarp();
    }
    if (lane < 16) g_idx[(b*2048 + n)*16 + lane] = ob[w][lane];
}

// ---------------- K_agg: x = g[j] + w1p@dp ; stats1 + max over K (launch #4) ----------------
// Warp per point. Indices via 4 broadcast int4 loads (no SHFL chain); 16 float2
// gathers batched with register headroom (launch_bounds 256,3).
__global__ void __launch_bounds__(256, 3) k_agg(const float* __restrict__ p,
                                                const float* __restrict__ w1) {
    __shared__ float ms[64*8];
    __shared__ __align__(16) float dps[8][16][4];
    __shared__ float s1s[64], q1s[64];
    int tid = threadIdx.x;
    if (tid < 64) { s1s[tid] = 0.f; q1s[tid] = 0.f; }
    __syncthreads();

    int b  = blockIdx.x >> 8;
    int n0 = (blockIdx.x & 255) << 3;
    int w = tid >> 5, lane = tid & 31;
    int n = n0 + w;
    int c0 = lane * 2;

    // indices: 4 uniform int4 loads, statically unpacked (no shfl)
    const int4* ip = (const int4*)(g_idx + (size_t)(b*2048 + n)*16);
    int4 j0 = __ldg(ip), j1 = __ldg(ip+1), j2 = __ldg(ip+2), j3 = __ldg(ip+3);
    int js[16] = {j0.x,j0.y,j0.z,j0.w, j1.x,j1.y,j1.z,j1.w,
                  j2.x,j2.y,j2.z,j2.w, j3.x,j3.y,j3.z,j3.w};

    float wx0 = w1[c0*67+0],     wy0 = w1[c0*67+1],     wz0 = w1[c0*67+2];
    float wx1 = w1[(c0+1)*67+0], wy1 = w1[(c0+1)*67+1], wz1 = w1[(c0+1)*67+2];
    const float* pc = p + (size_t)(b*2048 + n)*3;
    float cx = pc[0], cy = pc[1], cz = pc[2];

    // lanes 0-15 fetch their neighbor's coords and write dp to smem
    if (lane < 16) {
        int jr = g_idx[(b*2048 + n)*16 + lane];
        const float* pj = p + (size_t)(b*2048 + jr)*3;
        dps[w][lane][0] = pj[0] - cx;
        dps[w][lane][1] = pj[1] - cy;
        dps[w][lane][2] = pj[2] - cz;
    }

    // batched gather: 16 independent float2 loads in flight
    float2 gv[16];
    #pragma unroll
    for (int k = 0; k < 16; k++)
        gv[k] = __ldg((const float2*)(g_feat + (size_t)(b*2048 + js[k])*64 + c0));

    __syncwarp();

    float mx0 = -3.402823466e38f, mx1 = -3.402823466e38f;
    float s0 = 0.f, q0 = 0.f, s1v = 0.f, q1v = 0.f;
    #pragma unroll
    for (int k = 0; k < 16; k++) {
        float4 d = *(const float4*)&dps[w][k][0];   // broadcast, conflict-free
        float v0 = fmaf(wx0, d.x, fmaf(wy0, d.y, fmaf(wz0, d.z, gv[k].x)));
        float v1 = fmaf(wx1, d.x, fmaf(wy1, d.y, fmaf(wz1, d.z, gv[k].y)));
        mx0 = fmaxf(mx0, v0); mx1 = fmaxf(mx1, v1);
        s0 += v0;  q0  = fmaf(v0, v0, q0);
        s1v += v1; q1v = fmaf(v1, v1, q1v);
    }
    ms[c0*8 + w]     = mx0;
    ms[(c0+1)*8 + w] = mx1;
    atomicAdd(&s1s[c0],   s0);  atomicAdd(&q1s[c0],   q0);
    atomicAdd(&s1s[c0+1], s1v); atomicAdd(&q1s[c0+1], q1v);
    __syncthreads();
    for (int i = tid; i < 512; i += 256) {
        int c = i >> 3, nl = i & 7;
        g_m[(b*64 + c)*2048 + n0 + nl] = ms[i];
    }
    if (tid < 64) {
        atomicAdd(&g_s1[tid],  (double)s1s[tid]);
        atomicAdd(&g_ss1[tid], (double)q1s[tid]);
    }
}

// ---------------- K_mlp1 (HMMA): y[c0..c0+128, n0..n0+64] = w2 @ relu(bn1(m)) ----------------
#define M1_AH 2048
#define M1_AL 20480
#define M1_BH 38912
#define M1_BL 48128
#define M1_SMEM 57344
#define LDA1 72
#define LDB1 72
__global__ void __launch_bounds__(256) k_mlp1(const float* __restrict__ g1,
                                              const float* __restrict__ b1) {
    extern __shared__ __align__(16) char smem[];
    uint32_t sb = smem_u32(smem);
    float* sc  = (float*)(smem);
    float* sh  = (float*)(smem + 256);
    float* s2s = (float*)(smem + 512);
    float* q2s = (float*)(smem + 1024);
    int tid = threadIdx.x, wid = tid >> 5, lane = tid & 31;
    int b  = blockIdx.x >> 6;
    int ct = (blockIdx.x >> 5) & 1;
    int nt = blockIdx.x & 31;
    int c0 = ct << 7, n0 = nt << 6;
    int c_w = (wid & 3) << 5, n_w = (wid >> 2) << 5;

    uint4 pa_h[4], pa_l[4];
    #pragma unroll
    for (int j = 0; j < 4; j++) {
        int i = tid + j*256;
        int row = i >> 3, c8 = i & 7;
        pa_h[j] = ((const uint4*)(g_w2h + (size_t)(c0 + row)*64))[c8];
        pa_l[j] = ((const uint4*)(g_w2l + (size_t)(c0 + row)*64))[c8];
    }
    float2 pb[8];
    #pragma unroll
    for (int j = 0; j < 8; j++) {
        int i = tid + j*256;
        int k = i >> 5, np = i & 31;
        pb[j] = *(const float2*)&g_m[(b*64 + k)*2048 + n0 + np*2];
    }

    if (tid < 64) {
        double cnt = (double)(Bb*Nn*KK);
        double mu  = g_s1[tid] / cnt;
        double var = g_ss1[tid] / cnt - mu*mu;
        float s = g1[tid] * rsqrtf((float)var + EPSc);
        sc[tid] = s;
        sh[tid] = b1[tid] - (float)mu * s;
    }
    if (tid < 128) { s2s[tid] = 0.f; q2s[tid] = 0.f; }
    __syncthreads();

    #pragma unroll
    for (int j = 0; j < 4; j++) {
        int i = tid + j*256;
        int row = i >> 3, c8 = i & 7;
        *(uint4*)(smem + M1_AH + row*(LDA1*2) + c8*16) = pa_h[j];
        *(uint4*)(smem + M1_AL + row*(LDA1*2) + c8*16) = pa_l[j];
    }
    #pragma unroll
    for (int j = 0; j < 8; j++) {
        int i = tid + j*256;
        int k = i >> 5, np = i & 31;
        float sck = sc[k], shk = sh[k];
        float va = fmaxf(0.f, fmaf(pb[j].x, sck, shk));
        float vb = fmaxf(0.f, fmaf(pb[j].y, sck, shk));
        __nv_bfloat16 ha, la, hb, lb;
        split_bf16(va, ha, la);
        split_bf16(vb, hb, lb);
        *(uint32_t*)(smem + M1_BH + k*(LDB1*2) + np*4) = pack2(ha, hb);
        *(uint32_t*)(smem + M1_BL + k*(LDB1*2) + np*4) = pack2(la, lb);
    }
    __syncthreads();

    float acc[2][4][4];
    #pragma unroll
    for (int i = 0; i < 2; i++)
        #pragma unroll
        for (int j = 0; j < 4; j++)
            #pragma unroll
            for (int r = 0; r < 4; r++) acc[i][j][r] = 0.f;

    uint32_t arow = lane & 15, acol = (lane >> 4) << 3;
    uint32_t brow = lane & 15;
    #pragma unroll
    for (int ks = 0; ks < 4; ks++) {
        uint32_t bh[4][2], bl[4][2];
        #pragma unroll
        for (int ntl = 0; ntl < 4; ntl++) {
            uint32_t baddr = (ks*16 + brow)*(LDB1*2) + (n_w + ntl*8)*2;
            ldmB(bh[ntl], sb + M1_BH + baddr);
            ldmB(bl[ntl], sb + M1_BL + baddr);
        }
        #pragma unroll
        for (int mt = 0; mt < 2; mt++) {
            uint32_t aaddr = (c_w + mt*16 + arow)*(LDA1*2) + (ks*16 + acol)*2;
            uint32_t ah[4], al[4];
            ldmA(ah, sb + M1_AH + aaddr);
            ldmA(al, sb + M1_AL + aaddr);
            #pragma unroll
            for (int ntl = 0; ntl < 4; ntl++) {
                mma16816(acc[mt][ntl], ah, bh[ntl]);
                mma16816(acc[mt][ntl], ah, bl[ntl]);
                mma16816(acc[mt][ntl], al, bh[ntl]);
            }
        }
    }

    int g = lane >> 2, tcol = (lane & 3) * 2;
    #pragma unroll
    for (int mt = 0; mt < 2; mt++) {
        int r0 = c_w + mt*16 + g, r1 = r0 + 8;
        float s0 = 0.f, q0 = 0.f, s1v = 0.f, q1v = 0.f;
        #pragma unroll
        for (int ntl = 0; ntl < 4; ntl++) {
            float d0 = acc[mt][ntl][0], d1 = acc[mt][ntl][1];
            float d2 = acc[mt][ntl][2], d3 = acc[mt][ntl][3];
            int col = n_w + ntl*8 + tcol;
            *(float2*)&g_y[(size_t)(b*256 + c0 + r0)*2048 + n0 + col] = make_float2(d0, d1);
            *(float2*)&g_y[(size_t)(b*256 + c0 + r1)*2048 + n0 + col] = make_float2(d2, d3);
            s0 += d0 + d1; q0 = fmaf(d0, d0, fmaf(d1, d1, q0));
            s1v += d2 + d3; q1v = fmaf(d2, d2, fmaf(d3, d3, q1v));
        }
        atomicAdd(&s2s[r0], s0);  atomicAdd(&q2s[r0], q0);
        atomicAdd(&s2s[r1], s1v); atomicAdd(&q2s[r1], q1v);
    }
    __syncthreads();
    if (tid < 128) {
        atomicAdd(&g_s2[c0 + tid],  (double)s2s[tid]);
        atomicAdd(&g_ss2[c0 + tid], (double)q2s[tid]);
    }
}

// ---------------- K_mlp2 (HMMA): z[64c, n0..n0+64] = w3 @ relu(bn2(y)) ----------------
#define M2_AH 2560
#define M2_AL 11776
#define M2_BH 20992
#define M2_BL 30208
#define M2_SMEM 39424
#define LDA2 72
#define LDB2 72
__global__ void __launch_bounds__(256) k_mlp2(const float* __restrict__ g2,
                                              const float* __restrict__ b2) {
    extern __shared__ __align__(16) char smem[];
    uint32_t sb = smem_u32(smem);
    float* sc  = (float*)(smem);
    float* sh  = (float*)(smem + 1024);
    float* s3s = (float*)(smem + 2048);
    float* q3s = (float*)(smem + 2304);
    int tid = threadIdx.x, wid = tid >> 5, lane = tid & 31;
    int b  = blockIdx.x >> 5;
    int n0 = (blockIdx.x & 31) << 6;
    int c_w = (wid & 3) << 4;
    int n_w = (wid >> 2) << 5;

    {
        double cnt = (double)(Bb*Nn);
        double mu  = g_s2[tid] / cnt;
        double var = g_ss2[tid] / cnt - mu*mu;
        float s = g2[tid] * rsqrtf((float)var + EPSc);
        sc[tid] = s;
        sh[tid] = b2[tid] - (float)mu * s;
    }
    if (tid < 64) { s3s[tid] = 0.f; q3s[tid] = 0.f; }
    __syncthreads();

    float acc[4][4];
    #pragma unroll
    for (int i = 0; i < 4; i++)
        #pragma unroll
        for (int r = 0; r < 4; r++) acc[i][r] = 0.f;

    uint32_t arow = lane & 15, acol = (lane >> 4) << 3;
    uint32_t brow = lane & 15;

    for (int q = 0; q < 4; q++) {
        int k0 = q << 6;
        uint4 pa_h[2], pa_l[2];
        #pragma unroll
        for (int j = 0; j < 2; j++) {
            int i = tid + j*256;
            int row = i >> 3, c8 = i & 7;
            pa_h[j] = ((const uint4*)(g_w3h + (size_t)row*256 + k0))[c8];
            pa_l[j] = ((const uint4*)(g_w3l + (size_t)row*256 + k0))[c8];
        }
        float2 pbv[8];
        #pragma unroll
        for (int j = 0; j < 8; j++) {
            int i = tid + j*256;
            int k = i >> 5, np = i & 31;
            pbv[j] = *(const float2*)&g_y[(size_t)(b*256 + k0 + k)*2048 + n0 + np*2];
        }
        #pragma unroll
        for (int j = 0; j < 2; j++) {
            int i = tid + j*256;
            int row = i >> 3, c8 = i & 7;
            *(uint4*)(smem + M2_AH + row*(LDA2*2) + c8*16) = pa_h[j];
            *(uint4*)(smem + M2_AL + row*(LDA2*2) + c8*16) = pa_l[j];
        }
        #pragma unroll
        for (int j = 0; j < 8; j++) {
            int i = tid + j*256;
            int k = i >> 5, np = i & 31;
            int ch = k0 + k;
            float sck = sc[ch], shk = sh[ch];
            float va = fmaxf(0.f, fmaf(pbv[j].x, sck, shk));
            float vb = fmaxf(0.f, fmaf(pbv[j].y, sck, shk));
            __nv_bfloat16 ha, la, hb, lb;
            split_bf16(va, ha, la);
            split_bf16(vb, hb, lb);
            *(uint32_t*)(smem + M2_BH + k*(LDB2*2) + np*4) = pack2(ha, hb);
            *(uint32_t*)(smem + M2_BL + k*(LDB2*2) + np*4) = pack2(la, lb);
        }
        __syncthreads();

        #pragma unroll
        for (int ks = 0; ks < 4; ks++) {
            uint32_t bh[4][2], bl[4][2];
            #pragma unroll
            for (int ntl = 0; ntl < 4; ntl++) {
                uint32_t baddr = (ks*16 + brow)*(LDB2*2) + (n_w + ntl*8)*2;
                ldmB(bh[ntl], sb + M2_BH + baddr);
                ldmB(bl[ntl], sb + M2_BL + baddr);
            }
            uint32_t aaddr = (c_w + arow)*(LDA2*2) + (ks*16 + acol)*2;
            uint32_t ah[4], al[4];
            ldmA(ah, sb + M2_AH + aaddr);
            ldmA(al, sb + M2_AL + aaddr);
            #pragma unroll
            for (int ntl = 0; ntl < 4; ntl++) {
                mma16816(acc[ntl], ah, bh[ntl]);
                mma16816(acc[ntl], ah, bl[ntl]);
                mma16816(acc[ntl], al, bh[ntl]);
            }
        }
        __syncthreads();
    }

    int g = lane >> 2, tcol = (lane & 3) * 2;
    {
        int r0 = c_w + g, r1 = r0 + 8;
        float s0 = 0.f, q0 = 0.f, s1v = 0.f, q1v = 0.f;
        #pragma unroll
        for (int ntl = 0; ntl < 4; ntl++) {
            float d0 = acc[ntl][0], d1 = acc[ntl][1];
            float d2 = acc[ntl][2], d3 = acc[ntl][3];
            int col = n_w + ntl*8 + tcol;
            *(float2*)&g_z[(size_t)(b*64 + r0)*2048 + n0 + col] = make_float2(d0, d1);
            *(float2*)&g_z[(size_t)(b*64 + r1)*2048 + n0 + col] = make_float2(d2, d3);
            s0 += d0 + d1; q0 = fmaf(d0, d0, fmaf(d1, d1, q0));
            s1v += d2 + d3; q1v = fmaf(d2, d2, fmaf(d3, d3, q1v));
        }
        atomicAdd(&s3s[r0], s0);  atomicAdd(&q3s[r0], q0);
        atomicAdd(&s3s[r1], s1v); atomicAdd(&q3s[r1], q1v);
    }
    __syncthreads();
    if (tid < 64) {
        atomicAdd(&g_s3[tid],  (double)s3s[tid]);
        atomicAdd(&g_ss3[tid], (double)q3s[tid]);
    }
}

// ---------------- K_out: relu(bn3(z) + f) ----------------
__global__ void __launch_bounds__(256) k_out(const float* __restrict__ f,
                                             const float* __restrict__ g3,
                                             const float* __restrict__ b3,
                                             float* __restrict__ out) {
    __shared__ float sc[64], sh[64];
    int tid = threadIdx.x;
    if (tid < 64) {
        double cnt = (double)(Bb*Nn);
        double mu  = g_s3[tid] / cnt;
        double var = g_ss3[tid] / cnt - mu*mu;
        float s = g3[tid] * rsqrtf((float)var + EPSc);
        sc[tid] = s;
        sh[tid] = b3[tid] - (float)mu * s;
    }
    __syncthreads();
    int i = blockIdx.x * 256 + tid;
    int base = i * 4;
    int c = (base >> 11) & 63;
    float4 z  = *(const float4*)&g_z[base];
    float4 fv = *(const float4*)&f[base];
    float4 o;
    o.x = fmaxf(0.f, fmaf(z.x, sc[c], sh[c]) + fv.x);
    o.y = fmaxf(0.f, fmaf(z.y, sc[c], sh[c]) + fv.y);
    o.z = fmaxf(0.f, fmaf(z.z, sc[c], sh[c]) + fv.z);
    o.w = fmaxf(0.f, fmaf(z.w, sc[c], sh[c]) + fv.w);
    *(float4*)&out[base] = o;
}

// ---------------- launch ----------------
extern "C" void kernel_launch(void* const* d_in, const int* in_sizes, int n_in,
                              void* d_out, int out_size) {
    const float* p  = (const float*)d_in[0];
    const float* f  = (const float*)d_in[1];
    const float* w1 = (const float*)d_in[2];
    const float* g1 = (const float*)d_in[3];
    const float* b1 = (const float*)d_in[4];
    const float* w2 = (const float*)d_in[5];
    const float* g2 = (const float*)d_in[6];
    const float* b2 = (const float*)d_in[7];
    const float* w3 = (const float*)d_in[8];
    const float* g3 = (const float*)d_in[9];
    const float* b3 = (const float*)d_in[10];
    float* out = (float*)d_out;

    cudaFuncSetAttribute(k_mlp1, cudaFuncAttributeMaxDynamicSharedMemorySize, M1_SMEM);
    cudaFuncSetAttribute(k_mlp2, cudaFuncAttributeMaxDynamicSharedMemorySize, M2_SMEM);

    k_prep <<<64,   256>>>(w2, w3);
    k_gfeat<<<512,  256>>>(f, w1);
    k_ballq<<<512, 1024>>>(p);
    k_agg  <<<2048, 256>>>(p, w1);
    k_mlp1 <<<512,  256, M1_SMEM>>>(g1, b1);
    k_mlp2 <<<256,  256, M2_SMEM>>>(g2, b2);
    k_out  <<<1024, 256>>>(f, g3, b3, out);
}

// round 15
// speedup vs baseline: 1.2123x; 1.1073x over previous
#include <cuda_runtime.h>
#include <cuda_bf16.h>
#include <cstdint>

#define Bb   8
#define Nn   2048
#define Cc   64
#define MIDm 256
#define KK   16
#define R2c  0.0225f
#define EPSc 1e-5f

// ---------------- scratch (device globals, no allocation) ----------------
__device__ __align__(16) int    g_idx[Bb*Nn*KK];      // [b][n][16]
__device__ __align__(16) float  g_feat[Bb*Nn*Cc];     // [b][n][c]  = w1[:,3:]@f
__device__ __align__(16) float  g_m[Bb*Cc*Nn];        // [b][c][n]  = max_k x
__device__ __align__(16) float  g_y[Bb*MIDm*Nn];      // [b][c][n]
__device__ __align__(16) float  g_z[Bb*Cc*Nn];        // [b][c][n]
// split-bf16 weights (same layout as source, no transpose needed)
__device__ __align__(16) __nv_bfloat16 g_w2h[MIDm*Cc], g_w2l[MIDm*Cc];   // [o=256][k=64]
__device__ __align__(16) __nv_bfloat16 g_w3h[Cc*MIDm], g_w3l[Cc*MIDm];   // [c=64][k=256]
// striped stat accumulators (reduce same-address atomic contention)
__device__ double g_s1p[32][Cc],   g_ss1p[32][Cc];
__device__ double g_s2p[16][MIDm], g_ss2p[16][MIDm];
__device__ double g_s3p[16][Cc],   g_ss3p[16][Cc];

// ---------------- mma/ldmatrix helpers ----------------
__device__ __forceinline__ uint32_t smem_u32(const void* p) {
    uint32_t r;
    asm("{ .reg .u64 t; cvta.to.shared.u64 t, %1; cvt.u32.u64 %0, t; }" : "=r"(r) : "l"(p));
    return r;
}
__device__ __forceinline__ void ldmA(uint32_t* a, uint32_t addr) {   // x4 non-trans
    asm volatile("ldmatrix.sync.aligned.m8n8.x4.shared.b16 {%0,%1,%2,%3}, [%4];"
                 : "=r"(a[0]), "=r"(a[1]), "=r"(a[2]), "=r"(a[3]) : "r"(addr));
}
__device__ __forceinline__ void ldmB(uint32_t* b2, uint32_t addr) {  // x2 trans
    asm volatile("ldmatrix.sync.aligned.m8n8.x2.trans.shared.b16 {%0,%1}, [%2];"
                 : "=r"(b2[0]), "=r"(b2[1]) : "r"(addr));
}
__device__ __forceinline__ void mma16816(float* d, const uint32_t* a, const uint32_t* b2) {
    asm volatile(
        "mma.sync.aligned.m16n8k16.row.col.f32.bf16.bf16.f32 "
        "{%0,%1,%2,%3}, {%4,%5,%6,%7}, {%8,%9}, {%0,%1,%2,%3};"
        : "+f"(d[0]), "+f"(d[1]), "+f"(d[2]), "+f"(d[3])
        : "r"(a[0]), "r"(a[1]), "r"(a[2]), "r"(a[3]), "r"(b2[0]), "r"(b2[1]));
}
__device__ __forceinline__ void split_bf16(float v, __nv_bfloat16& h, __nv_bfloat16& l) {
    h = __float2bfloat16_rn(v);
    l = __float2bfloat16_rn(v - __bfloat162float(h));
}
__device__ __forceinline__ uint32_t pack2(__nv_bfloat16 a, __nv_bfloat16 b) {
    return (uint32_t)__bfloat16_as_ushort(a) | ((uint32_t)__bfloat16_as_ushort(b) << 16);
}

// ---------------- K_prep: split-bf16 weights + stripe zeroing ----------------
__global__ void __launch_bounds__(256) k_prep(const float* __restrict__ w2,
                                              const float* __restrict__ w3) {
    int i = blockIdx.x * 256 + threadIdx.x;   // 0..16383
    { __nv_bfloat16 h, l; split_bf16(w2[i], h, l); g_w2h[i] = h; g_w2l[i] = l; }
    { __nv_bfloat16 h, l; split_bf16(w3[i], h, l); g_w3h[i] = h; g_w3l[i] = l; }
    if (i < 32*Cc)   { ((double*)g_s1p)[i] = 0.0; ((double*)g_ss1p)[i] = 0.0; }
    if (i < 16*MIDm) { ((double*)g_s2p)[i] = 0.0; ((double*)g_ss2p)[i] = 0.0; }
    if (i < 16*Cc)   { ((double*)g_s3p)[i] = 0.0; ((double*)g_ss3p)[i] = 0.0; }
}

// ---------------- K_gfeat ----------------
__global__ void __launch_bounds__(256) k_gfeat(const float* __restrict__ f,
                                               const float* __restrict__ w1) {
    __shared__ __align__(16) float w1t[64*68];
    __shared__ __align__(16) float fs[64*32];
    __shared__ __align__(16) float gs[32*68];
    int tid = threadIdx.x;
    int b  = blockIdx.x >> 6;
    int n0 = (blockIdx.x & 63) << 5;

    for (int i = tid; i < 64*64; i += 256) {
        int c = i >> 6, cp = i & 63;
        w1t[cp*68 + c] = w1[c*67 + 3 + cp];
    }
    for (int i = tid; i < 64*32; i += 256) {
        int cp = i >> 5, nl = i & 31;
        fs[i] = f[(b*64 + cp)*2048 + n0 + nl];
    }
    __syncthreads();

    int nl = tid & 31, cg = tid >> 5;
    float acc[8];
    #pragma unroll
    for (int i = 0; i < 8; i++) acc[i] = 0.f;

    #pragma unroll 8
    for (int cp = 0; cp < 64; cp++) {
        float fv = fs[cp*32 + nl];
        float4 wa = *(const float4*)&w1t[cp*68 + cg*8];
        float4 wb = *(const float4*)&w1t[cp*68 + cg*8 + 4];
        acc[0] = fmaf(wa.x, fv, acc[0]);
        acc[1] = fmaf(wa.y, fv, acc[1]);
        acc[2] = fmaf(wa.z, fv, acc[2]);
        acc[3] = fmaf(wa.w, fv, acc[3]);
        acc[4] = fmaf(wb.x, fv, acc[4]);
        acc[5] = fmaf(wb.y, fv, acc[5]);
        acc[6] = fmaf(wb.z, fv, acc[6]);
        acc[7] = fmaf(wb.w, fv, acc[7]);
    }
    #pragma unroll
    for (int i = 0; i < 8; i++) gs[nl*68 + cg*8 + i] = acc[i];
    __syncthreads();
    for (int i = tid; i < 2048; i += 256) {
        int nn = i >> 6, c = i & 63;
        g_feat[(b*2048 + n0 + nn)*64 + c] = gs[nn*68 + c];
    }
}

// ---------------- K_ballq: 32 points per block ----------------
__global__ void __launch_bounds__(1024) k_ballq(const float* __restrict__ p) {
    __shared__ float px[2048], py[2048], pz[2048];
    __shared__ int   ob[32][16];
    int tid = threadIdx.x;
    int b  = blockIdx.x >> 6;
    int n0 = (blockIdx.x & 63) << 5;

    for (int i = tid; i < 2048; i += 1024) {
        const float* pp = p + (size_t)(b*2048 + i)*3;
        px[i] = pp[0]; py[i] = pp[1]; pz[i] = pp[2];
    }
    __syncthreads();

    int w = tid >> 5, lane = tid & 31;
    int n = n0 + w;
    float qx = px[n], qy = py[n], qz = pz[n];
    int cnt = 0;
    for (int j0 = 0; j0 < 2048; j0 += 32) {
        int j = j0 + lane;
        float dx = __fsub_rn(px[j], qx);
        float dy = __fsub_rn(py[j], qy);
        float dz = __fsub_rn(pz[j], qz);
        float d2 = __fadd_rn(__fadd_rn(__fmul_rn(dx,dx), __fmul_rn(dy,dy)), __fmul_rn(dz,dz));
        bool q = d2 < R2c;
        unsigned mask = __ballot_sync(0xffffffffu, q);
        if (mask) {
            int r = cnt + __popc(mask & ((1u << lane) - 1u));
            if (q && r < 16) ob[w][r] = j;
            cnt += __popc(mask);
            if (cnt >= 16) break;
        }
    }
    __syncwarp();
    if (cnt < 16) {
        int first = ob[w][0];
        if (lane >= cnt && lane < 16) ob[w][lane] = first;
        __syncwarp();
    }
    if (lane < 16) g_idx[(b*2048 + n)*16 + lane] = ob[w][lane];
}

// ---------------- K_agg: x = g[j] + w1p@dp ; stats1 + max over K ----------------
__global__ void __launch_bounds__(256, 3) k_agg(const float* __restrict__ p,
                                                const float* __restrict__ w1) {
    __shared__ float ms[64*8];
    __shared__ __align__(16) float dps[8][16][4];
    __shared__ float s1s[64], q1s[64];
    int tid = threadIdx.x;
    if (tid < 64) { s1s[tid] = 0.f; q1s[tid] = 0.f; }
    __syncthreads();

    int b  = blockIdx.x >> 8;
    int n0 = (blockIdx.x & 255) << 3;
    int w = tid >> 5, lane = tid & 31;
    int n = n0 + w;
    int c0 = lane * 2;

    // indices: 4 uniform int4 loads, statically unpacked (no shfl)
    const int4* ip = (const int4*)(g_idx + (size_t)(b*2048 + n)*16);
    int4 j0 = __ldg(ip), j1 = __ldg(ip+1), j2 = __ldg(ip+2), j3 = __ldg(ip+3);
    int js[16] = {j0.x,j0.y,j0.z,j0.w, j1.x,j1.y,j1.z,j1.w,
                  j2.x,j2.y,j2.z,j2.w, j3.x,j3.y,j3.z,j3.w};

    float wx0 = w1[c0*67+0],     wy0 = w1[c0*67+1],     wz0 = w1[c0*67+2];
    float wx1 = w1[(c0+1)*67+0], wy1 = w1[(c0+1)*67+1], wz1 = w1[(c0+1)*67+2];
    const float* pc = p + (size_t)(b*2048 + n)*3;
    float cx = pc[0], cy = pc[1], cz = pc[2];

    // lanes 0-15 fetch their neighbor's coords and write dp to smem
    if (lane < 16) {
        int jr = g_idx[(b*2048 + n)*16 + lane];
        const float* pj = p + (size_t)(b*2048 + jr)*3;
        dps[w][lane][0] = pj[0] - cx;
        dps[w][lane][1] = pj[1] - cy;
        dps[w][lane][2] = pj[2] - cz;
    }

    // batched gather: 16 independent float2 loads in flight
    float2 gv[16];
    #pragma unroll
    for (int k = 0; k < 16; k++)
        gv[k] = __ldg((const float2*)(g_feat + (size_t)(b*2048 + js[k])*64 + c0));

    __syncwarp();

    float mx0 = -3.402823466e38f, mx1 = -3.402823466e38f;
    float s0 = 0.f, q0 = 0.f, s1v = 0.f, q1v = 0.f;
    #pragma unroll
    for (int k = 0; k < 16; k++) {
        float4 d = *(const float4*)&dps[w][k][0];   // broadcast, conflict-free
        float v0 = fmaf(wx0, d.x, fmaf(wy0, d.y, fmaf(wz0, d.z, gv[k].x)));
        float v1 = fmaf(wx1, d.x, fmaf(wy1, d.y, fmaf(wz1, d.z, gv[k].y)));
        mx0 = fmaxf(mx0, v0); mx1 = fmaxf(mx1, v1);
        s0 += v0;  q0  = fmaf(v0, v0, q0);
        s1v += v1; q1v = fmaf(v1, v1, q1v);
    }
    ms[c0*8 + w]     = mx0;
    ms[(c0+1)*8 + w] = mx1;
    atomicAdd(&s1s[c0],   s0);  atomicAdd(&q1s[c0],   q0);
    atomicAdd(&s1s[c0+1], s1v); atomicAdd(&q1s[c0+1], q1v);
    __syncthreads();
    for (int i = tid; i < 512; i += 256) {
        int c = i >> 3, nl = i & 7;
        g_m[(b*64 + c)*2048 + n0 + nl] = ms[i];
    }
    if (tid < 64) {
        int st = blockIdx.x & 31;
        atomicAdd(&g_s1p[st][tid],  (double)s1s[tid]);
        atomicAdd(&g_ss1p[st][tid], (double)q1s[tid]);
    }
}

// ---------------- K_mlp1 (HMMA): y[c0..c0+128, n0..n0+64] = w2 @ relu(bn1(m)) ----------------
#define M1_AH 2048
#define M1_AL 20480
#define M1_BH 38912
#define M1_BL 48128
#define M1_SMEM 57344
#define LDA1 72
#define LDB1 72
__global__ void __launch_bounds__(256) k_mlp1(const float* __restrict__ g1,
                                              const float* __restrict__ b1) {
    extern __shared__ __align__(16) char smem[];
    uint32_t sb = smem_u32(smem);
    float* sc  = (float*)(smem);
    float* sh  = (float*)(smem + 256);
    float* s2s = (float*)(smem + 512);
    float* q2s = (float*)(smem + 1024);
    int tid = threadIdx.x, wid = tid >> 5, lane = tid & 31;
    int b  = blockIdx.x >> 6;
    int ct = (blockIdx.x >> 5) & 1;
    int nt = blockIdx.x & 31;
    int c0 = ct << 7, n0 = nt << 6;
    int c_w = (wid & 3) << 5, n_w = (wid >> 2) << 5;

    uint4 pa_h[4], pa_l[4];
    #pragma unroll
    for (int j = 0; j < 4; j++) {
        int i = tid + j*256;
        int row = i >> 3, c8 = i & 7;
        pa_h[j] = ((const uint4*)(g_w2h + (size_t)(c0 + row)*64))[c8];
        pa_l[j] = ((const uint4*)(g_w2l + (size_t)(c0 + row)*64))[c8];
    }
    float2 pb[8];
    #pragma unroll
    for (int j = 0; j < 8; j++) {
        int i = tid + j*256;
        int k = i >> 5, np = i & 31;
        pb[j] = *(const float2*)&g_m[(b*64 + k)*2048 + n0 + np*2];
    }

    if (tid < 64) {
        double sv = 0.0, qv = 0.0;
        #pragma unroll 8
        for (int st = 0; st < 32; st++) { sv += g_s1p[st][tid]; qv += g_ss1p[st][tid]; }
        double cnt = (double)(Bb*Nn*KK);
        double mu  = sv / cnt;
        double var = qv / cnt - mu*mu;
        float s = g1[tid] * rsqrtf((float)var + EPSc);
        sc[tid] = s;
        sh[tid] = b1[tid] - (float)mu * s;
    }
    if (tid < 128) { s2s[tid] = 0.f; q2s[tid] = 0.f; }
    __syncthreads();

    #pragma unroll
    for (int j = 0; j < 4; j++) {
        int i = tid + j*256;
        int row = i >> 3, c8 = i & 7;
        *(uint4*)(smem + M1_AH + row*(LDA1*2) + c8*16) = pa_h[j];
        *(uint4*)(smem + M1_AL + row*(LDA1*2) + c8*16) = pa_l[j];
    }
    #pragma unroll
    for (int j = 0; j < 8; j++) {
        int i = tid + j*256;
        int k = i >> 5, np = i & 31;
        float sck = sc[k], shk = sh[k];
        float va = fmaxf(0.f, fmaf(pb[j].x, sck, shk));
        float vb = fmaxf(0.f, fmaf(pb[j].y, sck, shk));
        __nv_bfloat16 ha, la, hb, lb;
        split_bf16(va, ha, la);
        split_bf16(vb, hb, lb);
        *(uint32_t*)(smem + M1_BH + k*(LDB1*2) + np*4) = pack2(ha, hb);
        *(uint32_t*)(smem + M1_BL + k*(LDB1*2) + np*4) = pack2(la, lb);
    }
    __syncthreads();

    float acc[2][4][4];
    #pragma unroll
    for (int i = 0; i < 2; i++)
        #pragma unroll
        for (int j = 0; j < 4; j++)
            #pragma unroll
            for (int r = 0; r < 4; r++) acc[i][j][r] = 0.f;

    uint32_t arow = lane & 15, acol = (lane >> 4) << 3;
    uint32_t brow = lane & 15;
    #pragma unroll
    for (int ks = 0; ks < 4; ks++) {
        uint32_t bh[4][2], bl[4][2];
        #pragma unroll
        for (int ntl = 0; ntl < 4; ntl++) {
            uint32_t baddr = (ks*16 + brow)*(LDB1*2) + (n_w + ntl*8)*2;
            ldmB(bh[ntl], sb + M1_BH + baddr);
            ldmB(bl[ntl], sb + M1_BL + baddr);
        }
        #pragma unroll
        for (int mt = 0; mt < 2; mt++) {
            uint32_t aaddr = (c_w + mt*16 + arow)*(LDA1*2) + (ks*16 + acol)*2;
            uint32_t ah[4], al[4];
            ldmA(ah, sb + M1_AH + aaddr);
            ldmA(al, sb + M1_AL + aaddr);
            #pragma unroll
            for (int ntl = 0; ntl < 4; ntl++) {
                mma16816(acc[mt][ntl], ah, bh[ntl]);
                mma16816(acc[mt][ntl], ah, bl[ntl]);
                mma16816(acc[mt][ntl], al, bh[ntl]);
            }
        }
    }

    int g = lane >> 2, tcol = (lane & 3) * 2;
    #pragma unroll
    for (int mt = 0; mt < 2; mt++) {
        int r0 = c_w + mt*16 + g, r1 = r0 + 8;
        float s0 = 0.f, q0 = 0.f, s1v = 0.f, q1v = 0.f;
        #pragma unroll
        for (int ntl = 0; ntl < 4; ntl++) {
            float d0 = acc[mt][ntl][0], d1 = acc[mt][ntl][1];
            float d2 = acc[mt][ntl][2], d3 = acc[mt][ntl][3];
            int col = n_w + ntl*8 + tcol;
            *(float2*)&g_y[(size_t)(b*256 + c0 + r0)*2048 + n0 + col] = make_float2(d0, d1);
            *(float2*)&g_y[(size_t)(b*256 + c0 + r1)*2048 + n0 + col] = make_float2(d2, d3);
            s0 += d0 + d1; q0 = fmaf(d0, d0, fmaf(d1, d1, q0));
            s1v += d2 + d3; q1v = fmaf(d2, d2, fmaf(d3, d3, q1v));
        }
        atomicAdd(&s2s[r0], s0);  atomicAdd(&q2s[r0], q0);
        atomicAdd(&s2s[r1], s1v); atomicAdd(&q2s[r1], q1v);
    }
    __syncthreads();
    if (tid < 128) {
        int st = blockIdx.x & 15;
        atomicAdd(&g_s2p[st][c0 + tid],  (double)s2s[tid]);
        atomicAdd(&g_ss2p[st][c0 + tid], (double)q2s[tid]);
    }
}

// ---------------- K_mlp2 (HMMA): z[64c, n0..n0+64] = w3 @ relu(bn2(y)) ----------------
#define M2_AH 2560
#define M2_AL 11776
#define M2_BH 20992
#define M2_BL 30208
#define M2_SMEM 39424
#define LDA2 72
#define LDB2 72
__global__ void __launch_bounds__(256) k_mlp2(const float* __restrict__ g2,
                                              const float* __restrict__ b2) {
    extern __shared__ __align__(16) char smem[];
    uint32_t sb = smem_u32(smem);
    float* sc  = (float*)(smem);
    float* sh  = (float*)(smem + 1024);
    float* s3s = (float*)(smem + 2048);
    float* q3s = (float*)(smem + 2304);
    int tid = threadIdx.x, wid = tid >> 5, lane = tid & 31;
    int b  = blockIdx.x >> 5;
    int n0 = (blockIdx.x & 31) << 6;
    int c_w = (wid & 3) << 4;
    int n_w = (wid >> 2) << 5;

    {
        double sv = 0.0, qv = 0.0;
        #pragma unroll 4
        for (int st = 0; st < 16; st++) { sv += g_s2p[st][tid]; qv += g_ss2p[st][tid]; }
        double cnt = (double)(Bb*Nn);
        double mu  = sv / cnt;
        double var = qv / cnt - mu*mu;
        float s = g2[tid] * rsqrtf((float)var + EPSc);
        sc[tid] = s;
        sh[tid] = b2[tid] - (float)mu * s;
    }
    if (tid < 64) { s3s[tid] = 0.f; q3s[tid] = 0.f; }
    __syncthreads();

    float acc[4][4];
    #pragma unroll
    for (int i = 0; i < 4; i++)
        #pragma unroll
        for (int r = 0; r < 4; r++) acc[i][r] = 0.f;

    uint32_t arow = lane & 15, acol = (lane >> 4) << 3;
    uint32_t brow = lane & 15;

    for (int q = 0; q < 4; q++) {
        int k0 = q << 6;
        uint4 pa_h[2], pa_l[2];
        #pragma unroll
        for (int j = 0; j < 2; j++) {
            int i = tid + j*256;
            int row = i >> 3, c8 = i & 7;
            pa_h[j] = ((const uint4*)(g_w3h + (size_t)row*256 + k0))[c8];
            pa_l[j] = ((const uint4*)(g_w3l + (size_t)row*256 + k0))[c8];
        }
        float2 pbv[8];
        #pragma unroll
        for (int j = 0; j < 8; j++) {
            int i = tid + j*256;
            int k = i >> 5, np = i & 31;
            pbv[j] = *(const float2*)&g_y[(size_t)(b*256 + k0 + k)*2048 + n0 + np*2];
        }
        #pragma unroll
        for (int j = 0; j < 2; j++) {
            int i = tid + j*256;
            int row = i >> 3, c8 = i & 7;
            *(uint4*)(smem + M2_AH + row*(LDA2*2) + c8*16) = pa_h[j];
            *(uint4*)(smem + M2_AL + row*(LDA2*2) + c8*16) = pa_l[j];
        }
        #pragma unroll
        for (int j = 0; j < 8; j++) {
            int i = tid + j*256;
            int k = i >> 5, np = i & 31;
            int ch = k0 + k;
            float sck = sc[ch], shk = sh[ch];
            float va = fmaxf(0.f, fmaf(pbv[j].x, sck, shk));
            float vb = fmaxf(0.f, fmaf(pbv[j].y, sck, shk));
            __nv_bfloat16 ha, la, hb, lb;
            split_bf16(va, ha, la);
            split_bf16(vb, hb, lb);
            *(uint32_t*)(smem + M2_BH + k*(LDB2*2) + np*4) = pack2(ha, hb);
            *(uint32_t*)(smem + M2_BL + k*(LDB2*2) + np*4) = pack2(la, lb);
        }
        __syncthreads();

        #pragma unroll
        for (int ks = 0; ks < 4; ks++) {
            uint32_t bh[4][2], bl[4][2];
            #pragma unroll
            for (int ntl = 0; ntl < 4; ntl++) {
                uint32_t baddr = (ks*16 + brow)*(LDB2*2) + (n_w + ntl*8)*2;
                ldmB(bh[ntl], sb + M2_BH + baddr);
                ldmB(bl[ntl], sb + M2_BL + baddr);
            }
            uint32_t aaddr = (c_w + arow)*(LDA2*2) + (ks*16 + acol)*2;
            uint32_t ah[4], al[4];
            ldmA(ah, sb + M2_AH + aaddr);
            ldmA(al, sb + M2_AL + aaddr);
            #pragma unroll
            for (int ntl = 0; ntl < 4; ntl++) {
                mma16816(acc[ntl], ah, bh[ntl]);
                mma16816(acc[ntl], ah, bl[ntl]);
                mma16816(acc[ntl], al, bh[ntl]);
            }
        }
        __syncthreads();
    }

    int g = lane >> 2, tcol = (lane & 3) * 2;
    {
        int r0 = c_w + g, r1 = r0 + 8;
        float s0 = 0.f, q0 = 0.f, s1v = 0.f, q1v = 0.f;
        #pragma unroll
        for (int ntl = 0; ntl < 4; ntl++) {
            float d0 = acc[ntl][0], d1 = acc[ntl][1];
            float d2 = acc[ntl][2], d3 = acc[ntl][3];
            int col = n_w + ntl*8 + tcol;
            *(float2*)&g_z[(size_t)(b*64 + r0)*2048 + n0 + col] = make_float2(d0, d1);
            *(float2*)&g_z[(size_t)(b*64 + r1)*2048 + n0 + col] = make_float2(d2, d3);
            s0 += d0 + d1; q0 = fmaf(d0, d0, fmaf(d1, d1, q0));
            s1v += d2 + d3; q1v = fmaf(d2, d2, fmaf(d3, d3, q1v));
        }
        atomicAdd(&s3s[r0], s0);  atomicAdd(&q3s[r0], q0);
        atomicAdd(&s3s[r1], s1v); atomicAdd(&q3s[r1], q1v);
    }
    __syncthreads();
    if (tid < 64) {
        int st = blockIdx.x & 15;
        atomicAdd(&g_s3p[st][tid],  (double)s3s[tid]);
        atomicAdd(&g_ss3p[st][tid], (double)q3s[tid]);
    }
}

// ---------------- K_out: relu(bn3(z) + f) ----------------
__global__ void __launch_bounds__(256) k_out(const float* __restrict__ f,
                                             const float* __restrict__ g3,
                                             const float* __restrict__ b3,
                                             float* __restrict__ out) {
    __shared__ float sc[64], sh[64];
    int tid = threadIdx.x;
    if (tid < 64) {
        double sv = 0.0, qv = 0.0;
        #pragma unroll 4
        for (int st = 0; st < 16; st++) { sv += g_s3p[st][tid]; qv += g_ss3p[st][tid]; }
        double cnt = (double)(Bb*Nn);
        double mu  = sv / cnt;
        double var = qv / cnt - mu*mu;
        float s = g3[tid] * rsqrtf((float)var + EPSc);
        sc[tid] = s;
        sh[tid] = b3[tid] - (float)mu * s;
    }
    __syncthreads();
    int i = blockIdx.x * 256 + tid;
    int base = i * 4;
    int c = (base >> 11) & 63;
    float4 z  = *(const float4*)&g_z[base];
    float4 fv = *(const float4*)&f[base];
    float4 o;
    o.x = fmaxf(0.f, fmaf(z.x, sc[c], sh[c]) + fv.x);
    o.y = fmaxf(0.f, fmaf(z.y, sc[c], sh[c]) + fv.y);
    o.z = fmaxf(0.f, fmaf(z.z, sc[c], sh[c]) + fv.z);
    o.w = fmaxf(0.f, fmaf(z.w, sc[c], sh[c]) + fv.w);
    *(float4*)&out[base] = o;
}

// ---------------- launch ----------------
extern "C" void kernel_launch(void* const* d_in, const int* in_sizes, int n_in,
                              void* d_out, int out_size) {
    const float* p  = (const float*)d_in[0];
    const float* f  = (const float*)d_in[1];
    const float* w1 = (const float*)d_in[2];
    const float* g1 = (const float*)d_in[3];
    const float* b1 = (const float*)d_in[4];
    const float* w2 = (const float*)d_in[5];
    const float* g2 = (const float*)d_in[6];
    const float* b2 = (const float*)d_in[7];
    const float* w3 = (const float*)d_in[8];
    const float* g3 = (const float*)d_in[9];
    const float* b3 = (const float*)d_in[10];
    float* out = (float*)d_out;

    cudaFuncSetAttribute(k_mlp1, cudaFuncAttributeMaxDynamicSharedMemorySize, M1_SMEM);
    cudaFuncSetAttribute(k_mlp2, cudaFuncAttributeMaxDynamicSharedMemorySize, M2_SMEM);

    k_prep <<<64,   256>>>(w2, w3);
    k_gfeat<<<512,  256>>>(f, w1);
    k_ballq<<<512, 1024>>>(p);
    k_agg  <<<2048, 256>>>(p, w1);
    k_mlp1 <<<512,  256, M1_SMEM>>>(g1, b1);
    k_mlp2 <<<256,  256, M2_SMEM>>>(g2, b2);
    k_out  <<<1024, 256>>>(f, g3, b3, out);
}